// round 12
// baseline (speedup 1.0000x reference)
#include <cuda_runtime.h>
#include <cuda_fp16.h>

#define NMAX 200000
#define EMAX 3200000
#define GMAX 1024

// ---- scratch (static device globals; no runtime allocation) ----
__device__ int     g_cnt[NMAX];
__device__ int     g_rowptr[NMAX + 1];   // pre-final (per-1024-block exclusive)
__device__ int     g_rowptr2[NMAX + 1];  // final CSR row pointers
__device__ int     g_rank[EMAX];
__device__ int     g_csr[EMAX];
__device__ int     g_bsums[1024];
__device__ int     g_gcnt[GMAX];
__device__ int     g_goff[GMAX];
__device__ float   g_dinv[NMAX];
__device__ __half2 g_xsh[NMAX * 8];    // layer-1 messages: 16 halves/row (9 real)
__device__ float   g_agg[NMAX * 16];   // layer-1 aggregated sums (fp32)
__device__ __half2 g_bufh[NMAX * 32];  // fp16 messages
__device__ __half2 g_zh[NMAX * 32];    // fp16 post-activation z (and final h3)

// -------------------- mma helpers --------------------

__device__ __forceinline__ void ldsm_x4(unsigned& a0, unsigned& a1, unsigned& a2,
                                        unsigned& a3, unsigned addr) {
    asm volatile("ldmatrix.sync.aligned.m8n8.x4.shared.b16 {%0,%1,%2,%3}, [%4];"
                 : "=r"(a0), "=r"(a1), "=r"(a2), "=r"(a3) : "r"(addr));
}
__device__ __forceinline__ void ldsm_x2_t(unsigned& b0, unsigned& b1, unsigned addr) {
    asm volatile("ldmatrix.sync.aligned.m8n8.x2.trans.shared.b16 {%0,%1}, [%2];"
                 : "=r"(b0), "=r"(b1) : "r"(addr));
}
__device__ __forceinline__ void mma_16816(float* c, unsigned a0, unsigned a1,
                                          unsigned a2, unsigned a3,
                                          unsigned b0, unsigned b1) {
    asm volatile("mma.sync.aligned.m16n8k16.row.col.f32.f16.f16.f32 "
                 "{%0,%1,%2,%3}, {%4,%5,%6,%7}, {%8,%9}, {%0,%1,%2,%3};"
                 : "+f"(c[0]), "+f"(c[1]), "+f"(c[2]), "+f"(c[3])
                 : "r"(a0), "r"(a1), "r"(a2), "r"(a3), "r"(b0), "r"(b1));
}

// -------------------- setup kernels --------------------

__global__ void k_count(const int* __restrict__ dst, const int* __restrict__ batch,
                        int n, int e) {
    int i = blockIdx.x * blockDim.x + threadIdx.x;
    int e4 = i * 4;
    if (e4 + 4 <= e) {
        int4 d = *reinterpret_cast<const int4*>(&dst[e4]);
        int4 r;
        r.x = atomicAdd(&g_cnt[d.x], 1);
        r.y = atomicAdd(&g_cnt[d.y], 1);
        r.z = atomicAdd(&g_cnt[d.z], 1);
        r.w = atomicAdd(&g_cnt[d.w], 1);
        *reinterpret_cast<int4*>(&g_rank[e4]) = r;
    } else {
        for (int q = e4; q < e; q++) g_rank[q] = atomicAdd(&g_cnt[dst[q]], 1);
    }
    int n4 = i * 4;
    if (n4 + 4 <= n) {
        int4 b = *reinterpret_cast<const int4*>(&batch[n4]);
        atomicAdd(&g_gcnt[b.x], 1);
        atomicAdd(&g_gcnt[b.y], 1);
        atomicAdd(&g_gcnt[b.z], 1);
        atomicAdd(&g_gcnt[b.w], 1);
    } else {
        for (int q = n4; q < n; q++) atomicAdd(&g_gcnt[batch[q]], 1);
    }
}

// per-1024-block scan of cnt; extra last block performs the graph-offset scan
__global__ void k_scanA(int n, int nb) {
    __shared__ int s[1024];
    int t = threadIdx.x;
    if ((int)blockIdx.x == nb) {
        int v = g_gcnt[t];
        s[t] = v;
        __syncthreads();
        #pragma unroll
        for (int off = 1; off < 1024; off <<= 1) {
            int u = (t >= off) ? s[t - off] : 0;
            __syncthreads();
            s[t] += u;
            __syncthreads();
        }
        g_goff[t] = s[t] - v;
        return;
    }
    int i = blockIdx.x * 1024 + t;
    int v = (i < n) ? g_cnt[i] : 0;
    s[t] = v;
    __syncthreads();
    #pragma unroll
    for (int off = 1; off < 1024; off <<= 1) {
        int u = (t >= off) ? s[t - off] : 0;
        __syncthreads();
        s[t] += u;
        __syncthreads();
    }
    if (i < n) g_rowptr[i] = s[t] - v;
    if (t == 1023) g_bsums[blockIdx.x] = s[1023];
}

// fused finalize: per-block redundant scan of block sums -> final rowptr2, dinv,
// fp16 xs messages, AND the CSR edge fill (using stable pre-final rowptr + sbx).
__global__ void k_finalize(const float* __restrict__ x,
                           const int* __restrict__ src, const int* __restrict__ dst,
                           int n, int e, int nb) {
    __shared__ int sb[256];
    __shared__ int sbx[256];
    int t = threadIdx.x;
    int bv = (t < nb) ? g_bsums[t] : 0;
    sb[t] = bv;
    __syncthreads();
    #pragma unroll
    for (int off = 1; off < 256; off <<= 1) {
        int u = (t >= off) ? sb[t - off] : 0;
        __syncthreads();
        sb[t] += u;
        __syncthreads();
    }
    sbx[t] = sb[t] - bv;  // exclusive block-sum prefix
    __syncthreads();

    // node slice: final rowptr2, dinv, fp16 layer-1 messages
    int i = blockIdx.x * 256 + t;
    if (i < n) {
        g_rowptr2[i] = g_rowptr[i] + sbx[i >> 10];
        float dv = rsqrtf((float)(g_cnt[i] + 1));
        g_dinv[i] = dv;
        __half2 h[8];
        #pragma unroll
        for (int k = 0; k < 8; k++) {
            float f0 = (2 * k     < 9) ? dv * x[i * 9 + 2 * k]     : 0.f;
            float f1 = (2 * k + 1 < 9) ? dv * x[i * 9 + 2 * k + 1] : 0.f;
            h[k] = __floats2half2_rn(f0, f1);
        }
        *reinterpret_cast<uint4*>(&g_xsh[i * 8])     = *reinterpret_cast<uint4*>(&h[0]);
        *reinterpret_cast<uint4*>(&g_xsh[i * 8 + 4]) = *reinterpret_cast<uint4*>(&h[4]);
    }
    if (blockIdx.x == 0 && t == 0) g_rowptr2[n] = sb[255];

    // edge fill (grid-stride, 4 edges per iteration); pre-final g_rowptr is stable
    int gid = blockIdx.x * 256 + t;
    int nth = gridDim.x * 256;
    int e4cnt = e >> 2;
    for (int q = gid; q < e4cnt; q += nth) {
        int base = q * 4;
        int4 d = *reinterpret_cast<const int4*>(&dst[base]);
        int4 s = *reinterpret_cast<const int4*>(&src[base]);
        int4 r = *reinterpret_cast<const int4*>(&g_rank[base]);
        g_csr[__ldg(&g_rowptr[d.x]) + sbx[d.x >> 10] + r.x] = s.x;
        g_csr[__ldg(&g_rowptr[d.y]) + sbx[d.y >> 10] + r.y] = s.y;
        g_csr[__ldg(&g_rowptr[d.z]) + sbx[d.z >> 10] + r.z] = s.z;
        g_csr[__ldg(&g_rowptr[d.w]) + sbx[d.w >> 10] + r.w] = s.w;
    }
    if (blockIdx.x == 0 && t == 0) {
        for (int q = e4cnt * 4; q < e; q++) {
            int d = dst[q];
            g_csr[g_rowptr[d] + sbx[d >> 10] + g_rank[q]] = src[q];
        }
    }
}

// -------------------- layer kernels --------------------

// layer-1 fp16 aggregation: 4 nodes per warp; 8 lanes per node (half2)
__global__ __launch_bounds__(256) void k_gather9h(int n) {
    int gw = (blockIdx.x * blockDim.x + threadIdx.x) >> 5;
    int lane = threadIdx.x & 31;
    int grp = lane >> 3, gl = lane & 7;
    int v = gw * 4 + grp;
    if (v >= n) return;
    int beg = g_rowptr2[v], end = g_rowptr2[v + 1];
    float2 p = __half22float2(__ldg(&g_xsh[v * 8 + gl]));
    float ax = p.x, ay = p.y;
    int e = beg;
    for (; e + 8 <= end; e += 8) {
        int s[8];
        #pragma unroll
        for (int q = 0; q < 8; q++) s[q] = __ldg(&g_csr[e + q]);
        #pragma unroll
        for (int q = 0; q < 8; q++) {
            float2 w = __half22float2(__ldg(&g_xsh[s[q] * 8 + gl]));
            ax += w.x; ay += w.y;
        }
    }
    for (; e < end; e++) {
        int s = __ldg(&g_csr[e]);
        float2 w = __half22float2(__ldg(&g_xsh[s * 8 + gl]));
        ax += w.x; ay += w.y;
    }
    *reinterpret_cast<float2*>(&g_agg[v * 16 + gl * 2]) = make_float2(ax, ay);
}

// fp16 gather + fused epilogue: z[v] = relu(dinv*(self+neighbors) + bias), fp16 out
// 4 nodes per warp; 8 lanes per node, each lane covers 8 feats (uint4)
__global__ __launch_bounds__(256) void k_gather_z(const float* __restrict__ bias, int n) {
    int gw = (blockIdx.x * blockDim.x + threadIdx.x) >> 5;
    int lane = threadIdx.x & 31;
    int quad = lane >> 3, ql = lane & 7;
    int v = gw * 4 + quad;
    if (v >= n) return;
    int beg = g_rowptr2[v], end = g_rowptr2[v + 1];
    const uint4* buf = reinterpret_cast<const uint4*>(g_bufh);
    uint4 u = __ldg(&buf[v * 8 + ql]);   // self-loop
    float2 p0 = __half22float2(*reinterpret_cast<__half2*>(&u.x));
    float2 p1 = __half22float2(*reinterpret_cast<__half2*>(&u.y));
    float2 p2 = __half22float2(*reinterpret_cast<__half2*>(&u.z));
    float2 p3 = __half22float2(*reinterpret_cast<__half2*>(&u.w));
    float a0 = p0.x, a1 = p0.y, a2 = p1.x, a3 = p1.y;
    float a4 = p2.x, a5 = p2.y, a6 = p3.x, a7 = p3.y;
    int e = beg;
    for (; e + 8 <= end; e += 8) {
        int s[8];
        #pragma unroll
        for (int q = 0; q < 8; q++) s[q] = __ldg(&g_csr[e + q]);
        #pragma unroll
        for (int q = 0; q < 8; q++) {
            uint4 w = __ldg(&buf[s[q] * 8 + ql]);
            float2 q0 = __half22float2(*reinterpret_cast<__half2*>(&w.x));
            float2 q1 = __half22float2(*reinterpret_cast<__half2*>(&w.y));
            float2 q2 = __half22float2(*reinterpret_cast<__half2*>(&w.z));
            float2 q3 = __half22float2(*reinterpret_cast<__half2*>(&w.w));
            a0 += q0.x; a1 += q0.y; a2 += q1.x; a3 += q1.y;
            a4 += q2.x; a5 += q2.y; a6 += q3.x; a7 += q3.y;
        }
    }
    for (; e < end; e++) {
        int s = __ldg(&g_csr[e]);
        uint4 w = __ldg(&buf[s * 8 + ql]);
        float2 q0 = __half22float2(*reinterpret_cast<__half2*>(&w.x));
        float2 q1 = __half22float2(*reinterpret_cast<__half2*>(&w.y));
        float2 q2 = __half22float2(*reinterpret_cast<__half2*>(&w.z));
        float2 q3 = __half22float2(*reinterpret_cast<__half2*>(&w.w));
        a0 += q0.x; a1 += q0.y; a2 += q1.x; a3 += q1.y;
        a4 += q2.x; a5 += q2.y; a6 += q3.x; a7 += q3.y;
    }
    // fused epilogue: z = relu(dinv*a + b) in fp16
    float dv = g_dinv[v];
    float4 b0 = __ldg(&reinterpret_cast<const float4*>(bias)[ql * 2]);
    float4 b1 = __ldg(&reinterpret_cast<const float4*>(bias)[ql * 2 + 1]);
    __half2 h[4];
    h[0] = __floats2half2_rn(fmaxf(fmaf(dv, a0, b0.x), 0.f), fmaxf(fmaf(dv, a1, b0.y), 0.f));
    h[1] = __floats2half2_rn(fmaxf(fmaf(dv, a2, b0.z), 0.f), fmaxf(fmaf(dv, a3, b0.w), 0.f));
    h[2] = __floats2half2_rn(fmaxf(fmaf(dv, a4, b1.x), 0.f), fmaxf(fmaf(dv, a5, b1.y), 0.f));
    h[3] = __floats2half2_rn(fmaxf(fmaf(dv, a6, b1.z), 0.f), fmaxf(fmaf(dv, a7, b1.w), 0.f));
    *reinterpret_cast<uint4*>(&g_zh[v * 32 + ql * 4]) = *reinterpret_cast<uint4*>(h);
}

// shared HMMA stage: out = Zs(fp16, 72-stride) @ Ws(fp16, 72-stride);
// messages dst[v] = half(dinv*out). 8 warps: 4 m-tiles x 2 n-tiles.
__device__ __forceinline__ void mma_stage(const __half* Zs, const __half* Ws,
                                          const float* dvs, int base, int n,
                                          int tid, __half2* __restrict__ dst) {
    int lane = tid & 31, wid = tid >> 5;
    int mt = wid & 3, nt = wid >> 2;
    float acc[4][4] = {};
    unsigned zbase = (unsigned)__cvta_generic_to_shared(Zs);
    unsigned wbase = (unsigned)__cvta_generic_to_shared(Ws);
    #pragma unroll
    for (int k = 0; k < 4; k++) {
        unsigned a0, a1, a2, a3;
        int arow = mt * 16 + (lane & 15);
        ldsm_x4(a0, a1, a2, a3, zbase + (arow * 72 + k * 16 + (lane >> 4) * 8) * 2);
        #pragma unroll
        for (int t = 0; t < 4; t++) {
            unsigned b0, b1;
            int brow = k * 16 + (lane & 15);
            ldsm_x2_t(b0, b1, wbase + (brow * 72 + nt * 32 + t * 8) * 2);
            mma_16816(acc[t], a0, a1, a2, a3, b0, b1);
        }
    }
    int r0 = mt * 16 + (lane >> 2), r1 = r0 + 8;
    int cp = lane & 3;
    float dv0 = dvs[r0], dv1 = dvs[r1];
    int v0 = base + r0, v1 = base + r1;
    #pragma unroll
    for (int t = 0; t < 4; t++) {
        int colpair = nt * 16 + t * 4 + cp;
        if (v0 < n)
            dst[v0 * 32 + colpair] = __floats2half2_rn(dv0 * acc[t][0], dv0 * acc[t][1]);
        if (v1 < n)
            dst[v1 * 32 + colpair] = __floats2half2_rn(dv1 * acc[t][2], dv1 * acc[t][3]);
    }
}

// layer 1: z1 = relu(dinv*(agg@W1)+b1) (fp32, 9-dim); msgs = half(dinv*(z1@W2)) via HMMA
__global__ __launch_bounds__(256) void k_l1_mma(const float* __restrict__ W1,
                                                const float* __restrict__ b1,
                                                const float* __restrict__ W2, int n) {
    __shared__ float W1s[9 * 64];
    __shared__ float A9s[64 * 16];
    __shared__ float dvs[64];
    __shared__ float b1s[64];
    __shared__ __half Zs[64 * 72];
    __shared__ __half Ws[64 * 72];
    int tid = threadIdx.x;
    int base = blockIdx.x * 64;
    for (int i = tid; i < 576; i += 256) W1s[i] = W1[i];
    if (tid < 64) {
        int v = base + tid;
        dvs[tid] = (v < n) ? g_dinv[v] : 0.f;
        b1s[tid] = b1[tid];
    }
    for (int i = tid; i < 4096; i += 256) {
        int k = i >> 6, f = i & 63;
        Ws[k * 72 + f] = __float2half(W2[i]);
    }
    for (int i = tid; i < 1024; i += 256) {
        int nl = i >> 4, k = i & 15;
        int v = base + nl;
        A9s[i] = (v < n) ? g_agg[v * 16 + k] : 0.f;
    }
    __syncthreads();
    for (int i = tid; i < 4096; i += 256) {
        int nl = i >> 6, f = i & 63;
        float s = 0.f;
        #pragma unroll
        for (int k = 0; k < 9; k++) s = fmaf(A9s[nl * 16 + k], W1s[k * 64 + f], s);
        Zs[nl * 72 + f] = __float2half(fmaxf(fmaf(dvs[nl], s, b1s[f]), 0.f));
    }
    __syncthreads();
    mma_stage(Zs, Ws, dvs, base, n, tid, g_bufh);
}

// middle layer: msgs = half(dinv*(z@W)) via HMMA, z read fp16 from g_zh
__global__ __launch_bounds__(256) void k_tf_mma(const float* __restrict__ W, int n) {
    __shared__ __half Zs[64 * 72];
    __shared__ __half Ws[64 * 72];
    __shared__ float dvs[64];
    int tid = threadIdx.x;
    int base = blockIdx.x * 64;
    if (tid < 64) {
        int v = base + tid;
        dvs[tid] = (v < n) ? g_dinv[v] : 0.f;
    }
    for (int i = tid; i < 4096; i += 256) {
        int k = i >> 6, f = i & 63;
        Ws[k * 72 + f] = __float2half(W[i]);
    }
    for (int i = tid; i < 512; i += 256) {
        int r = i >> 3, q = i & 7;
        int v = base + r;
        uint4 val = (v < n) ? *reinterpret_cast<const uint4*>(&g_zh[v * 32 + q * 4])
                            : make_uint4(0, 0, 0, 0);
        *reinterpret_cast<uint4*>(&Zs[r * 72 + q * 8]) = val;
    }
    __syncthreads();
    mma_stage(Zs, Ws, dvs, base, n, tid, g_bufh);
}

// pooling + head: h3 fp16 in g_zh; 32 partials x 32 feat-pairs
__global__ __launch_bounds__(1024) void k_pool(const float* __restrict__ Wl,
                                               const float* __restrict__ bl,
                                               float* __restrict__ outp) {
    __shared__ float ssum[32][64];
    __shared__ float smax[32][64];
    __shared__ float pooled[128];
    int g = blockIdx.x, tid = threadIdx.x;
    int fp = tid & 31, part = tid >> 5;
    int beg = g_goff[g], cnt = g_gcnt[g];
    float sx = 0.f, sy = 0.f, mx = 0.f, my = 0.f;
    for (int i = part; i < cnt; i += 32) {
        int v = beg + i;
        float2 h = __half22float2(__ldg(&g_zh[v * 32 + fp]));
        sx += h.x; sy += h.y;
        mx = fmaxf(mx, h.x); my = fmaxf(my, h.y);
    }
    ssum[part][fp * 2] = sx; ssum[part][fp * 2 + 1] = sy;
    smax[part][fp * 2] = mx; smax[part][fp * 2 + 1] = my;
    __syncthreads();
    if (tid < 64) {
        float s = 0.f, m = 0.f;
        #pragma unroll
        for (int w = 0; w < 32; w++) {
            s += ssum[w][tid];
            m = fmaxf(m, smax[w][tid]);
        }
        pooled[tid] = s / fmaxf((float)cnt, 1.f);
        pooled[64 + tid] = m;
    }
    __syncthreads();
    if (tid < 64) {
        float o = bl[tid];
        #pragma unroll 8
        for (int k = 0; k < 128; k++) o = fmaf(pooled[k], Wl[k * 64 + tid], o);
        outp[g * 64 + tid] = o;
    }
}

// -------------------- launcher --------------------

extern "C" void kernel_launch(void* const* d_in, const int* in_sizes, int n_in,
                              void* d_out, int out_size) {
    const float* x     = (const float*)d_in[0];
    const int*   ei    = (const int*)  d_in[1];
    const int*   batch = (const int*)  d_in[3];
    const float* W1    = (const float*)d_in[4];
    const float* b1    = (const float*)d_in[5];
    const float* W2    = (const float*)d_in[6];
    const float* b2    = (const float*)d_in[7];
    const float* W3    = (const float*)d_in[8];
    const float* b3    = (const float*)d_in[9];
    const float* Wl    = (const float*)d_in[10];
    const float* bl    = (const float*)d_in[11];
    float* out = (float*)d_out;

    int n = in_sizes[0] / 9;
    int e = in_sizes[1] / 2;
    const int* src = ei;
    const int* dst = ei + e;

    int gn  = (n + 255) / 256;
    int nb  = (n + 1023) / 1024;
    int ge4 = (e / 4 + 255) / 256 + 1;
    int gw4 = ((n + 3) / 4 * 32 + 255) / 256;

    // zero counters via memset nodes (no kernel launch)
    static void* p_cnt = nullptr;
    static void* p_gcnt = nullptr;
    if (!p_cnt) {
        cudaGetSymbolAddress(&p_cnt, g_cnt);
        cudaGetSymbolAddress(&p_gcnt, g_gcnt);
    }
    cudaMemsetAsync(p_cnt, 0, (size_t)n * sizeof(int));
    cudaMemsetAsync(p_gcnt, 0, (size_t)GMAX * sizeof(int));

    // graph structure
    k_count<<<ge4, 256>>>(dst, batch, n, e);
    k_scanA<<<nb + 1, 1024>>>(n, nb);
    k_finalize<<<gn, 256>>>(x, src, dst, n, e, nb);

    // layer 1: 9-dim gather + (W1, relu, W2) transform -> messages
    k_gather9h<<<gw4, 256>>>(n);
    k_l1_mma<<<(n + 63) / 64, 256>>>(W1, b1, W2, n);
    // layer 2: gather + epilogue(b2) -> z2; z2@W3 -> messages
    k_gather_z<<<gw4, 256>>>(b2, n);
    k_tf_mma<<<(n + 63) / 64, 256>>>(W3, n);
    // layer 3: gather + epilogue(b3) -> h3
    k_gather_z<<<gw4, 256>>>(b3, n);
    // pooling + head
    k_pool<<<GMAX, 1024>>>(Wl, bl, out);
}

// round 13
// speedup vs baseline: 1.0177x; 1.0177x over previous
#include <cuda_runtime.h>
#include <cuda_fp16.h>

#define NMAX 200000
#define EMAX 3200000
#define GMAX 1024

// ---- scratch (static device globals; no runtime allocation) ----
__device__ int     g_cnt[NMAX];
__device__ int     g_rowptr[NMAX + 1];
__device__ int     g_rank[EMAX];
__device__ int     g_csr[EMAX];
__device__ int     g_bsums[1024];
__device__ int     g_gcnt[GMAX];
__device__ int     g_goff[GMAX];
__device__ float   g_dinv[NMAX];
__device__ __half2 g_xsh[NMAX * 8];    // layer-1 messages: 16 halves/row (9 real)
__device__ float   g_agg[NMAX * 16];   // layer-1 aggregated sums (fp32)
__device__ __half2 g_bufh[NMAX * 32];  // fp16 messages
__device__ __half2 g_zh[NMAX * 32];    // fp16 post-activation z (and final h3)

// -------------------- mma helpers --------------------

__device__ __forceinline__ void ldsm_x4(unsigned& a0, unsigned& a1, unsigned& a2,
                                        unsigned& a3, unsigned addr) {
    asm volatile("ldmatrix.sync.aligned.m8n8.x4.shared.b16 {%0,%1,%2,%3}, [%4];"
                 : "=r"(a0), "=r"(a1), "=r"(a2), "=r"(a3) : "r"(addr));
}
__device__ __forceinline__ void ldsm_x2_t(unsigned& b0, unsigned& b1, unsigned addr) {
    asm volatile("ldmatrix.sync.aligned.m8n8.x2.trans.shared.b16 {%0,%1}, [%2];"
                 : "=r"(b0), "=r"(b1) : "r"(addr));
}
__device__ __forceinline__ void mma_16816(float* c, unsigned a0, unsigned a1,
                                          unsigned a2, unsigned a3,
                                          unsigned b0, unsigned b1) {
    asm volatile("mma.sync.aligned.m16n8k16.row.col.f32.f16.f16.f32 "
                 "{%0,%1,%2,%3}, {%4,%5,%6,%7}, {%8,%9}, {%0,%1,%2,%3};"
                 : "+f"(c[0]), "+f"(c[1]), "+f"(c[2]), "+f"(c[3])
                 : "r"(a0), "r"(a1), "r"(a2), "r"(a3), "r"(b0), "r"(b1));
}

// -------------------- setup kernels --------------------

__global__ void k_count(const int* __restrict__ dst, const int* __restrict__ batch,
                        int n, int e) {
    int i = blockIdx.x * blockDim.x + threadIdx.x;
    int e4 = i * 4;
    if (e4 + 4 <= e) {
        int4 d = *reinterpret_cast<const int4*>(&dst[e4]);
        int4 r;
        r.x = atomicAdd(&g_cnt[d.x], 1);
        r.y = atomicAdd(&g_cnt[d.y], 1);
        r.z = atomicAdd(&g_cnt[d.z], 1);
        r.w = atomicAdd(&g_cnt[d.w], 1);
        *reinterpret_cast<int4*>(&g_rank[e4]) = r;
    } else {
        for (int q = e4; q < e; q++) g_rank[q] = atomicAdd(&g_cnt[dst[q]], 1);
    }
    int n4 = i * 4;
    if (n4 + 4 <= n) {
        int4 b = *reinterpret_cast<const int4*>(&batch[n4]);
        atomicAdd(&g_gcnt[b.x], 1);
        atomicAdd(&g_gcnt[b.y], 1);
        atomicAdd(&g_gcnt[b.z], 1);
        atomicAdd(&g_gcnt[b.w], 1);
    } else {
        for (int q = n4; q < n; q++) atomicAdd(&g_gcnt[batch[q]], 1);
    }
}

// per-1024-block scan of cnt; extra last block performs the graph-offset scan
__global__ void k_scanA(int n, int nb) {
    __shared__ int s[1024];
    int t = threadIdx.x;
    if ((int)blockIdx.x == nb) {
        int v = g_gcnt[t];
        s[t] = v;
        __syncthreads();
        #pragma unroll
        for (int off = 1; off < 1024; off <<= 1) {
            int u = (t >= off) ? s[t - off] : 0;
            __syncthreads();
            s[t] += u;
            __syncthreads();
        }
        g_goff[t] = s[t] - v;
        return;
    }
    int i = blockIdx.x * 1024 + t;
    int v = (i < n) ? g_cnt[i] : 0;
    s[t] = v;
    __syncthreads();
    #pragma unroll
    for (int off = 1; off < 1024; off <<= 1) {
        int u = (t >= off) ? s[t - off] : 0;
        __syncthreads();
        s[t] += u;
        __syncthreads();
    }
    if (i < n) g_rowptr[i] = s[t] - v;
    if (t == 1023) g_bsums[blockIdx.x] = s[1023];
}

// fused: scan block sums in-block, finalize rowptr, dinv, fp16 xs messages
__global__ void k_scanC(const float* __restrict__ x, int n, int nb) {
    __shared__ int sb[256];
    __shared__ int sbx[256];
    int t = threadIdx.x;
    int bv = (t < nb) ? g_bsums[t] : 0;
    sb[t] = bv;
    __syncthreads();
    #pragma unroll
    for (int off = 1; off < 256; off <<= 1) {
        int u = (t >= off) ? sb[t - off] : 0;
        __syncthreads();
        sb[t] += u;
        __syncthreads();
    }
    sbx[t] = sb[t] - bv;
    __syncthreads();
    int i = blockIdx.x * 256 + t;
    if (i < n) {
        g_rowptr[i] += sbx[i >> 10];
        float dv = rsqrtf((float)(g_cnt[i] + 1));
        g_dinv[i] = dv;
        __half2 h[8];
        #pragma unroll
        for (int k = 0; k < 8; k++) {
            float f0 = (2 * k     < 9) ? dv * x[i * 9 + 2 * k]     : 0.f;
            float f1 = (2 * k + 1 < 9) ? dv * x[i * 9 + 2 * k + 1] : 0.f;
            h[k] = __floats2half2_rn(f0, f1);
        }
        *reinterpret_cast<uint4*>(&g_xsh[i * 8])     = *reinterpret_cast<uint4*>(&h[0]);
        *reinterpret_cast<uint4*>(&g_xsh[i * 8 + 4]) = *reinterpret_cast<uint4*>(&h[4]);
    }
    if (blockIdx.x == 0 && t == 0) g_rowptr[n] = sb[255];
}

__global__ void k_fill(const int* __restrict__ src, const int* __restrict__ dst, int e) {
    int i = blockIdx.x * blockDim.x + threadIdx.x;
    int e4 = i * 4;
    if (e4 + 4 <= e) {
        int4 d = *reinterpret_cast<const int4*>(&dst[e4]);
        int4 s = *reinterpret_cast<const int4*>(&src[e4]);
        int4 r = *reinterpret_cast<const int4*>(&g_rank[e4]);
        g_csr[__ldg(&g_rowptr[d.x]) + r.x] = s.x;
        g_csr[__ldg(&g_rowptr[d.y]) + r.y] = s.y;
        g_csr[__ldg(&g_rowptr[d.z]) + r.z] = s.z;
        g_csr[__ldg(&g_rowptr[d.w]) + r.w] = s.w;
    } else {
        for (int q = e4; q < e; q++)
            g_csr[__ldg(&g_rowptr[dst[q]]) + g_rank[q]] = src[q];
    }
}

// -------------------- layer kernels --------------------

// layer-1 fp16 aggregation: 4 nodes per warp; 8 lanes per node (half2)
__global__ __launch_bounds__(256) void k_gather9h(int n) {
    int gw = (blockIdx.x * blockDim.x + threadIdx.x) >> 5;
    int lane = threadIdx.x & 31;
    int grp = lane >> 3, gl = lane & 7;
    int v = gw * 4 + grp;
    if (v >= n) return;
    int beg = g_rowptr[v], end = g_rowptr[v + 1];
    float2 p = __half22float2(__ldg(&g_xsh[v * 8 + gl]));
    float ax = p.x, ay = p.y;
    int e = beg;
    for (; e + 8 <= end; e += 8) {
        int s[8];
        #pragma unroll
        for (int q = 0; q < 8; q++) s[q] = __ldg(&g_csr[e + q]);
        #pragma unroll
        for (int q = 0; q < 8; q++) {
            float2 w = __half22float2(__ldg(&g_xsh[s[q] * 8 + gl]));
            ax += w.x; ay += w.y;
        }
    }
    for (; e < end; e++) {
        int s = __ldg(&g_csr[e]);
        float2 w = __half22float2(__ldg(&g_xsh[s * 8 + gl]));
        ax += w.x; ay += w.y;
    }
    *reinterpret_cast<float2*>(&g_agg[v * 16 + gl * 2]) = make_float2(ax, ay);
}

// fp16 gather + fused epilogue: z[v] = relu(dinv*(self+neighbors) + bias), fp16 out
// 4 nodes per warp; 8 lanes per node, each lane covers 8 feats (uint4)
__global__ __launch_bounds__(256) void k_gather_z(const float* __restrict__ bias, int n) {
    int gw = (blockIdx.x * blockDim.x + threadIdx.x) >> 5;
    int lane = threadIdx.x & 31;
    int quad = lane >> 3, ql = lane & 7;
    int v = gw * 4 + quad;
    if (v >= n) return;
    int beg = g_rowptr[v], end = g_rowptr[v + 1];
    const uint4* buf = reinterpret_cast<const uint4*>(g_bufh);
    uint4 u = __ldg(&buf[v * 8 + ql]);   // self-loop
    float2 p0 = __half22float2(*reinterpret_cast<__half2*>(&u.x));
    float2 p1 = __half22float2(*reinterpret_cast<__half2*>(&u.y));
    float2 p2 = __half22float2(*reinterpret_cast<__half2*>(&u.z));
    float2 p3 = __half22float2(*reinterpret_cast<__half2*>(&u.w));
    float a0 = p0.x, a1 = p0.y, a2 = p1.x, a3 = p1.y;
    float a4 = p2.x, a5 = p2.y, a6 = p3.x, a7 = p3.y;
    int e = beg;
    for (; e + 8 <= end; e += 8) {
        int s[8];
        #pragma unroll
        for (int q = 0; q < 8; q++) s[q] = __ldg(&g_csr[e + q]);
        #pragma unroll
        for (int q = 0; q < 8; q++) {
            uint4 w = __ldg(&buf[s[q] * 8 + ql]);
            float2 q0 = __half22float2(*reinterpret_cast<__half2*>(&w.x));
            float2 q1 = __half22float2(*reinterpret_cast<__half2*>(&w.y));
            float2 q2 = __half22float2(*reinterpret_cast<__half2*>(&w.z));
            float2 q3 = __half22float2(*reinterpret_cast<__half2*>(&w.w));
            a0 += q0.x; a1 += q0.y; a2 += q1.x; a3 += q1.y;
            a4 += q2.x; a5 += q2.y; a6 += q3.x; a7 += q3.y;
        }
    }
    for (; e < end; e++) {
        int s = __ldg(&g_csr[e]);
        uint4 w = __ldg(&buf[s * 8 + ql]);
        float2 q0 = __half22float2(*reinterpret_cast<__half2*>(&w.x));
        float2 q1 = __half22float2(*reinterpret_cast<__half2*>(&w.y));
        float2 q2 = __half22float2(*reinterpret_cast<__half2*>(&w.z));
        float2 q3 = __half22float2(*reinterpret_cast<__half2*>(&w.w));
        a0 += q0.x; a1 += q0.y; a2 += q1.x; a3 += q1.y;
        a4 += q2.x; a5 += q2.y; a6 += q3.x; a7 += q3.y;
    }
    // fused epilogue: z = relu(dinv*a + b) in fp16
    float dv = g_dinv[v];
    float4 b0 = __ldg(&reinterpret_cast<const float4*>(bias)[ql * 2]);
    float4 b1 = __ldg(&reinterpret_cast<const float4*>(bias)[ql * 2 + 1]);
    __half2 h[4];
    h[0] = __floats2half2_rn(fmaxf(fmaf(dv, a0, b0.x), 0.f), fmaxf(fmaf(dv, a1, b0.y), 0.f));
    h[1] = __floats2half2_rn(fmaxf(fmaf(dv, a2, b0.z), 0.f), fmaxf(fmaf(dv, a3, b0.w), 0.f));
    h[2] = __floats2half2_rn(fmaxf(fmaf(dv, a4, b1.x), 0.f), fmaxf(fmaf(dv, a5, b1.y), 0.f));
    h[3] = __floats2half2_rn(fmaxf(fmaf(dv, a6, b1.z), 0.f), fmaxf(fmaf(dv, a7, b1.w), 0.f));
    *reinterpret_cast<uint4*>(&g_zh[v * 32 + ql * 4]) = *reinterpret_cast<uint4*>(h);
}

// shared HMMA stage: out = Zs(fp16, 72-stride) @ Ws(fp16, 72-stride);
// messages dst[v] = half(dinv*out). 8 warps: 4 m-tiles x 2 n-tiles.
__device__ __forceinline__ void mma_stage(const __half* Zs, const __half* Ws,
                                          const float* dvs, int base, int n,
                                          int tid, __half2* __restrict__ dst) {
    int lane = tid & 31, wid = tid >> 5;
    int mt = wid & 3, nt = wid >> 2;
    float acc[4][4] = {};
    unsigned zbase = (unsigned)__cvta_generic_to_shared(Zs);
    unsigned wbase = (unsigned)__cvta_generic_to_shared(Ws);
    #pragma unroll
    for (int k = 0; k < 4; k++) {
        unsigned a0, a1, a2, a3;
        int arow = mt * 16 + (lane & 15);
        ldsm_x4(a0, a1, a2, a3, zbase + (arow * 72 + k * 16 + (lane >> 4) * 8) * 2);
        #pragma unroll
        for (int t = 0; t < 4; t++) {
            unsigned b0, b1;
            int brow = k * 16 + (lane & 15);
            ldsm_x2_t(b0, b1, wbase + (brow * 72 + nt * 32 + t * 8) * 2);
            mma_16816(acc[t], a0, a1, a2, a3, b0, b1);
        }
    }
    int r0 = mt * 16 + (lane >> 2), r1 = r0 + 8;
    int cp = lane & 3;
    float dv0 = dvs[r0], dv1 = dvs[r1];
    int v0 = base + r0, v1 = base + r1;
    #pragma unroll
    for (int t = 0; t < 4; t++) {
        int colpair = nt * 16 + t * 4 + cp;
        if (v0 < n)
            dst[v0 * 32 + colpair] = __floats2half2_rn(dv0 * acc[t][0], dv0 * acc[t][1]);
        if (v1 < n)
            dst[v1 * 32 + colpair] = __floats2half2_rn(dv1 * acc[t][2], dv1 * acc[t][3]);
    }
}

// layer 1: z1 = relu(dinv*(agg@W1)+b1) (fp32, 9-dim); msgs = half(dinv*(z1@W2)) via HMMA
__global__ __launch_bounds__(256) void k_l1_mma(const float* __restrict__ W1,
                                                const float* __restrict__ b1,
                                                const float* __restrict__ W2, int n) {
    __shared__ float W1s[9 * 64];
    __shared__ float A9s[64 * 16];
    __shared__ float dvs[64];
    __shared__ float b1s[64];
    __shared__ __half Zs[64 * 72];
    __shared__ __half Ws[64 * 72];
    int tid = threadIdx.x;
    int base = blockIdx.x * 64;
    for (int i = tid; i < 576; i += 256) W1s[i] = W1[i];
    if (tid < 64) {
        int v = base + tid;
        dvs[tid] = (v < n) ? g_dinv[v] : 0.f;
        b1s[tid] = b1[tid];
    }
    for (int i = tid; i < 4096; i += 256) {
        int k = i >> 6, f = i & 63;
        Ws[k * 72 + f] = __float2half(W2[i]);
    }
    for (int i = tid; i < 1024; i += 256) {
        int nl = i >> 4, k = i & 15;
        int v = base + nl;
        A9s[i] = (v < n) ? g_agg[v * 16 + k] : 0.f;
    }
    __syncthreads();
    for (int i = tid; i < 4096; i += 256) {
        int nl = i >> 6, f = i & 63;
        float s = 0.f;
        #pragma unroll
        for (int k = 0; k < 9; k++) s = fmaf(A9s[nl * 16 + k], W1s[k * 64 + f], s);
        Zs[nl * 72 + f] = __float2half(fmaxf(fmaf(dvs[nl], s, b1s[f]), 0.f));
    }
    __syncthreads();
    mma_stage(Zs, Ws, dvs, base, n, tid, g_bufh);
}

// middle layer: msgs = half(dinv*(z@W)) via HMMA, z read fp16 from g_zh
__global__ __launch_bounds__(256) void k_tf_mma(const float* __restrict__ W, int n) {
    __shared__ __half Zs[64 * 72];
    __shared__ __half Ws[64 * 72];
    __shared__ float dvs[64];
    int tid = threadIdx.x;
    int base = blockIdx.x * 64;
    if (tid < 64) {
        int v = base + tid;
        dvs[tid] = (v < n) ? g_dinv[v] : 0.f;
    }
    for (int i = tid; i < 4096; i += 256) {
        int k = i >> 6, f = i & 63;
        Ws[k * 72 + f] = __float2half(W[i]);
    }
    for (int i = tid; i < 512; i += 256) {
        int r = i >> 3, q = i & 7;
        int v = base + r;
        uint4 val = (v < n) ? *reinterpret_cast<const uint4*>(&g_zh[v * 32 + q * 4])
                            : make_uint4(0, 0, 0, 0);
        *reinterpret_cast<uint4*>(&Zs[r * 72 + q * 8]) = val;
    }
    __syncthreads();
    mma_stage(Zs, Ws, dvs, base, n, tid, g_bufh);
}

// pooling + head: h3 fp16 in g_zh; 32 partials x 32 feat-pairs
__global__ __launch_bounds__(1024) void k_pool(const float* __restrict__ Wl,
                                               const float* __restrict__ bl,
                                               float* __restrict__ outp) {
    __shared__ float ssum[32][64];
    __shared__ float smax[32][64];
    __shared__ float pooled[128];
    int g = blockIdx.x, tid = threadIdx.x;
    int fp = tid & 31, part = tid >> 5;
    int beg = g_goff[g], cnt = g_gcnt[g];
    float sx = 0.f, sy = 0.f, mx = 0.f, my = 0.f;
    for (int i = part; i < cnt; i += 32) {
        int v = beg + i;
        float2 h = __half22float2(__ldg(&g_zh[v * 32 + fp]));
        sx += h.x; sy += h.y;
        mx = fmaxf(mx, h.x); my = fmaxf(my, h.y);
    }
    ssum[part][fp * 2] = sx; ssum[part][fp * 2 + 1] = sy;
    smax[part][fp * 2] = mx; smax[part][fp * 2 + 1] = my;
    __syncthreads();
    if (tid < 64) {
        float s = 0.f, m = 0.f;
        #pragma unroll
        for (int w = 0; w < 32; w++) {
            s += ssum[w][tid];
            m = fmaxf(m, smax[w][tid]);
        }
        pooled[tid] = s / fmaxf((float)cnt, 1.f);
        pooled[64 + tid] = m;
    }
    __syncthreads();
    if (tid < 64) {
        float o = bl[tid];
        #pragma unroll 8
        for (int k = 0; k < 128; k++) o = fmaf(pooled[k], Wl[k * 64 + tid], o);
        outp[g * 64 + tid] = o;
    }
}

// -------------------- launcher --------------------

extern "C" void kernel_launch(void* const* d_in, const int* in_sizes, int n_in,
                              void* d_out, int out_size) {
    const float* x     = (const float*)d_in[0];
    const int*   ei    = (const int*)  d_in[1];
    const int*   batch = (const int*)  d_in[3];
    const float* W1    = (const float*)d_in[4];
    const float* b1    = (const float*)d_in[5];
    const float* W2    = (const float*)d_in[6];
    const float* b2    = (const float*)d_in[7];
    const float* W3    = (const float*)d_in[8];
    const float* b3    = (const float*)d_in[9];
    const float* Wl    = (const float*)d_in[10];
    const float* bl    = (const float*)d_in[11];
    float* out = (float*)d_out;

    int n = in_sizes[0] / 9;
    int e = in_sizes[1] / 2;
    const int* src = ei;
    const int* dst = ei + e;

    int gn  = (n + 255) / 256;
    int nb  = (n + 1023) / 1024;
    int ge4 = (e / 4 + 255) / 256 + 1;
    int gw4 = ((n + 3) / 4 * 32 + 255) / 256;

    // zero counters via memset nodes (replaces the k_zero kernel launch)
    static void* p_cnt = nullptr;
    static void* p_gcnt = nullptr;
    if (!p_cnt) {
        cudaGetSymbolAddress(&p_cnt, g_cnt);
        cudaGetSymbolAddress(&p_gcnt, g_gcnt);
    }
    cudaMemsetAsync(p_cnt, 0, (size_t)n * sizeof(int));
    cudaMemsetAsync(p_gcnt, 0, (size_t)GMAX * sizeof(int));

    // graph structure
    k_count<<<ge4, 256>>>(dst, batch, n, e);
    k_scanA<<<nb + 1, 1024>>>(n, nb);
    k_scanC<<<gn, 256>>>(x, n, nb);
    k_fill<<<ge4, 256>>>(src, dst, e);

    // layer 1: 9-dim gather + (W1, relu, W2) transform -> messages
    k_gather9h<<<gw4, 256>>>(n);
    k_l1_mma<<<(n + 63) / 64, 256>>>(W1, b1, W2, n);
    // layer 2: gather + epilogue(b2) -> z2; z2@W3 -> messages
    k_gather_z<<<gw4, 256>>>(b2, n);
    k_tf_mma<<<(n + 63) / 64, 256>>>(W3, n);
    // layer 3: gather + epilogue(b3) -> h3
    k_gather_z<<<gw4, 256>>>(b3, n);
    // pooling + head
    k_pool<<<GMAX, 1024>>>(Wl, bl, out);
}

// round 14
// speedup vs baseline: 1.0196x; 1.0019x over previous
#include <cuda_runtime.h>
#include <cuda_fp16.h>

#define NMAX 200000
#define EMAX 3200000
#define GMAX 1024

// ---- scratch (static device globals; no runtime allocation) ----
__device__ int     g_cnt[NMAX];
__device__ int     g_rowptr[NMAX + 1];   // pre-final (per-1024-block exclusive)
__device__ int     g_rowptr2[NMAX + 1];  // final CSR row pointers
__device__ int     g_rank[EMAX];
__device__ int     g_csr[EMAX];
__device__ int     g_bsums[1024];
__device__ int     g_gcnt[GMAX];
__device__ int     g_goff[GMAX];
__device__ float   g_dinv[NMAX];
__device__ __half2 g_xsh[NMAX * 8];    // layer-1 messages: 16 halves/row (9 real)
__device__ float   g_agg[NMAX * 16];   // layer-1 aggregated sums (fp32)
__device__ __half2 g_bufh[NMAX * 32];  // fp16 messages
__device__ __half2 g_zh[NMAX * 32];    // fp16 post-activation z (and final h3)

// -------------------- mma helpers --------------------

__device__ __forceinline__ void ldsm_x4(unsigned& a0, unsigned& a1, unsigned& a2,
                                        unsigned& a3, unsigned addr) {
    asm volatile("ldmatrix.sync.aligned.m8n8.x4.shared.b16 {%0,%1,%2,%3}, [%4];"
                 : "=r"(a0), "=r"(a1), "=r"(a2), "=r"(a3) : "r"(addr));
}
__device__ __forceinline__ void ldsm_x2_t(unsigned& b0, unsigned& b1, unsigned addr) {
    asm volatile("ldmatrix.sync.aligned.m8n8.x2.trans.shared.b16 {%0,%1}, [%2];"
                 : "=r"(b0), "=r"(b1) : "r"(addr));
}
__device__ __forceinline__ void mma_16816(float* c, unsigned a0, unsigned a1,
                                          unsigned a2, unsigned a3,
                                          unsigned b0, unsigned b1) {
    asm volatile("mma.sync.aligned.m16n8k16.row.col.f32.f16.f16.f32 "
                 "{%0,%1,%2,%3}, {%4,%5,%6,%7}, {%8,%9}, {%0,%1,%2,%3};"
                 : "+f"(c[0]), "+f"(c[1]), "+f"(c[2]), "+f"(c[3])
                 : "r"(a0), "r"(a1), "r"(a2), "r"(a3), "r"(b0), "r"(b1));
}

// -------------------- setup kernels --------------------

__global__ void k_zero(int n) {
    int i = blockIdx.x * blockDim.x + threadIdx.x;
    if (i < n) g_cnt[i] = 0;
    if (i < GMAX) g_gcnt[i] = 0;
}

__global__ void k_count(const int* __restrict__ dst, const int* __restrict__ batch,
                        int n, int e) {
    int i = blockIdx.x * blockDim.x + threadIdx.x;
    int e4 = i * 4;
    if (e4 + 4 <= e) {
        int4 d = *reinterpret_cast<const int4*>(&dst[e4]);
        int4 r;
        r.x = atomicAdd(&g_cnt[d.x], 1);
        r.y = atomicAdd(&g_cnt[d.y], 1);
        r.z = atomicAdd(&g_cnt[d.z], 1);
        r.w = atomicAdd(&g_cnt[d.w], 1);
        *reinterpret_cast<int4*>(&g_rank[e4]) = r;
    } else {
        for (int q = e4; q < e; q++) g_rank[q] = atomicAdd(&g_cnt[dst[q]], 1);
    }
    int n4 = i * 4;
    if (n4 + 4 <= n) {
        int4 b = *reinterpret_cast<const int4*>(&batch[n4]);
        atomicAdd(&g_gcnt[b.x], 1);
        atomicAdd(&g_gcnt[b.y], 1);
        atomicAdd(&g_gcnt[b.z], 1);
        atomicAdd(&g_gcnt[b.w], 1);
    } else {
        for (int q = n4; q < n; q++) atomicAdd(&g_gcnt[batch[q]], 1);
    }
}

// per-1024-block scan of cnt; extra last block performs the graph-offset scan
__global__ void k_scanA(int n, int nb) {
    __shared__ int s[1024];
    int t = threadIdx.x;
    if ((int)blockIdx.x == nb) {
        int v = g_gcnt[t];
        s[t] = v;
        __syncthreads();
        #pragma unroll
        for (int off = 1; off < 1024; off <<= 1) {
            int u = (t >= off) ? s[t - off] : 0;
            __syncthreads();
            s[t] += u;
            __syncthreads();
        }
        g_goff[t] = s[t] - v;
        return;
    }
    int i = blockIdx.x * 1024 + t;
    int v = (i < n) ? g_cnt[i] : 0;
    s[t] = v;
    __syncthreads();
    #pragma unroll
    for (int off = 1; off < 1024; off <<= 1) {
        int u = (t >= off) ? s[t - off] : 0;
        __syncthreads();
        s[t] += u;
        __syncthreads();
    }
    if (i < n) g_rowptr[i] = s[t] - v;
    if (t == 1023) g_bsums[blockIdx.x] = s[1023];
}

// scan block sums in-block; write FINAL pointers to g_rowptr2 (g_rowptr untouched),
// plus dinv and fp16 xs messages. Runs concurrently with k_fill.
__global__ void k_scanC(const float* __restrict__ x, int n, int nb) {
    __shared__ int sb[256];
    __shared__ int sbx[256];
    int t = threadIdx.x;
    int bv = (t < nb) ? g_bsums[t] : 0;
    sb[t] = bv;
    __syncthreads();
    #pragma unroll
    for (int off = 1; off < 256; off <<= 1) {
        int u = (t >= off) ? sb[t - off] : 0;
        __syncthreads();
        sb[t] += u;
        __syncthreads();
    }
    sbx[t] = sb[t] - bv;
    __syncthreads();
    int i = blockIdx.x * 256 + t;
    if (i < n) {
        g_rowptr2[i] = g_rowptr[i] + sbx[i >> 10];
        float dv = rsqrtf((float)(g_cnt[i] + 1));
        g_dinv[i] = dv;
        __half2 h[8];
        #pragma unroll
        for (int k = 0; k < 8; k++) {
            float f0 = (2 * k     < 9) ? dv * x[i * 9 + 2 * k]     : 0.f;
            float f1 = (2 * k + 1 < 9) ? dv * x[i * 9 + 2 * k + 1] : 0.f;
            h[k] = __floats2half2_rn(f0, f1);
        }
        *reinterpret_cast<uint4*>(&g_xsh[i * 8])     = *reinterpret_cast<uint4*>(&h[0]);
        *reinterpret_cast<uint4*>(&g_xsh[i * 8 + 4]) = *reinterpret_cast<uint4*>(&h[4]);
    }
    if (blockIdx.x == 0 && t == 0) g_rowptr2[n] = sb[255];
}

// rank-based fill; recomputes the 256-entry block-sum prefix per block so it
// depends ONLY on scanA (runs concurrently with scanC on another stream).
__global__ __launch_bounds__(256) void k_fill(const int* __restrict__ src,
                                              const int* __restrict__ dst,
                                              int e, int nb) {
    __shared__ int sb[256];
    __shared__ int sbx[256];
    int t = threadIdx.x;
    int bv = (t < nb) ? g_bsums[t] : 0;
    sb[t] = bv;
    __syncthreads();
    #pragma unroll
    for (int off = 1; off < 256; off <<= 1) {
        int u = (t >= off) ? sb[t - off] : 0;
        __syncthreads();
        sb[t] += u;
        __syncthreads();
    }
    sbx[t] = sb[t] - bv;
    __syncthreads();
    int i = blockIdx.x * 256 + t;
    int e4 = i * 4;
    if (e4 + 4 <= e) {
        int4 d = *reinterpret_cast<const int4*>(&dst[e4]);
        int4 s = *reinterpret_cast<const int4*>(&src[e4]);
        int4 r = *reinterpret_cast<const int4*>(&g_rank[e4]);
        g_csr[__ldg(&g_rowptr[d.x]) + sbx[d.x >> 10] + r.x] = s.x;
        g_csr[__ldg(&g_rowptr[d.y]) + sbx[d.y >> 10] + r.y] = s.y;
        g_csr[__ldg(&g_rowptr[d.z]) + sbx[d.z >> 10] + r.z] = s.z;
        g_csr[__ldg(&g_rowptr[d.w]) + sbx[d.w >> 10] + r.w] = s.w;
    } else if (e4 < e) {
        for (int q = e4; q < e; q++) {
            int d = dst[q];
            g_csr[__ldg(&g_rowptr[d]) + sbx[d >> 10] + g_rank[q]] = src[q];
        }
    }
}

// -------------------- layer kernels --------------------

// layer-1 fp16 aggregation: 4 nodes per warp; 8 lanes per node (half2)
__global__ __launch_bounds__(256) void k_gather9h(int n) {
    int gw = (blockIdx.x * blockDim.x + threadIdx.x) >> 5;
    int lane = threadIdx.x & 31;
    int grp = lane >> 3, gl = lane & 7;
    int v = gw * 4 + grp;
    if (v >= n) return;
    int beg = g_rowptr2[v], end = g_rowptr2[v + 1];
    float2 p = __half22float2(__ldg(&g_xsh[v * 8 + gl]));
    float ax = p.x, ay = p.y;
    int e = beg;
    for (; e + 8 <= end; e += 8) {
        int s[8];
        #pragma unroll
        for (int q = 0; q < 8; q++) s[q] = __ldg(&g_csr[e + q]);
        #pragma unroll
        for (int q = 0; q < 8; q++) {
            float2 w = __half22float2(__ldg(&g_xsh[s[q] * 8 + gl]));
            ax += w.x; ay += w.y;
        }
    }
    for (; e < end; e++) {
        int s = __ldg(&g_csr[e]);
        float2 w = __half22float2(__ldg(&g_xsh[s * 8 + gl]));
        ax += w.x; ay += w.y;
    }
    *reinterpret_cast<float2*>(&g_agg[v * 16 + gl * 2]) = make_float2(ax, ay);
}

// fp16 gather + fused epilogue: z[v] = relu(dinv*(self+neighbors) + bias), fp16 out
// 4 nodes per warp; 8 lanes per node, each lane covers 8 feats (uint4)
__global__ __launch_bounds__(256) void k_gather_z(const float* __restrict__ bias, int n) {
    int gw = (blockIdx.x * blockDim.x + threadIdx.x) >> 5;
    int lane = threadIdx.x & 31;
    int quad = lane >> 3, ql = lane & 7;
    int v = gw * 4 + quad;
    if (v >= n) return;
    int beg = g_rowptr2[v], end = g_rowptr2[v + 1];
    const uint4* buf = reinterpret_cast<const uint4*>(g_bufh);
    uint4 u = __ldg(&buf[v * 8 + ql]);   // self-loop
    float2 p0 = __half22float2(*reinterpret_cast<__half2*>(&u.x));
    float2 p1 = __half22float2(*reinterpret_cast<__half2*>(&u.y));
    float2 p2 = __half22float2(*reinterpret_cast<__half2*>(&u.z));
    float2 p3 = __half22float2(*reinterpret_cast<__half2*>(&u.w));
    float a0 = p0.x, a1 = p0.y, a2 = p1.x, a3 = p1.y;
    float a4 = p2.x, a5 = p2.y, a6 = p3.x, a7 = p3.y;
    int e = beg;
    for (; e + 8 <= end; e += 8) {
        int s[8];
        #pragma unroll
        for (int q = 0; q < 8; q++) s[q] = __ldg(&g_csr[e + q]);
        #pragma unroll
        for (int q = 0; q < 8; q++) {
            uint4 w = __ldg(&buf[s[q] * 8 + ql]);
            float2 q0 = __half22float2(*reinterpret_cast<__half2*>(&w.x));
            float2 q1 = __half22float2(*reinterpret_cast<__half2*>(&w.y));
            float2 q2 = __half22float2(*reinterpret_cast<__half2*>(&w.z));
            float2 q3 = __half22float2(*reinterpret_cast<__half2*>(&w.w));
            a0 += q0.x; a1 += q0.y; a2 += q1.x; a3 += q1.y;
            a4 += q2.x; a5 += q2.y; a6 += q3.x; a7 += q3.y;
        }
    }
    for (; e < end; e++) {
        int s = __ldg(&g_csr[e]);
        uint4 w = __ldg(&buf[s * 8 + ql]);
        float2 q0 = __half22float2(*reinterpret_cast<__half2*>(&w.x));
        float2 q1 = __half22float2(*reinterpret_cast<__half2*>(&w.y));
        float2 q2 = __half22float2(*reinterpret_cast<__half2*>(&w.z));
        float2 q3 = __half22float2(*reinterpret_cast<__half2*>(&w.w));
        a0 += q0.x; a1 += q0.y; a2 += q1.x; a3 += q1.y;
        a4 += q2.x; a5 += q2.y; a6 += q3.x; a7 += q3.y;
    }
    // fused epilogue: z = relu(dinv*a + b) in fp16
    float dv = g_dinv[v];
    float4 b0 = __ldg(&reinterpret_cast<const float4*>(bias)[ql * 2]);
    float4 b1 = __ldg(&reinterpret_cast<const float4*>(bias)[ql * 2 + 1]);
    __half2 h[4];
    h[0] = __floats2half2_rn(fmaxf(fmaf(dv, a0, b0.x), 0.f), fmaxf(fmaf(dv, a1, b0.y), 0.f));
    h[1] = __floats2half2_rn(fmaxf(fmaf(dv, a2, b0.z), 0.f), fmaxf(fmaf(dv, a3, b0.w), 0.f));
    h[2] = __floats2half2_rn(fmaxf(fmaf(dv, a4, b1.x), 0.f), fmaxf(fmaf(dv, a5, b1.y), 0.f));
    h[3] = __floats2half2_rn(fmaxf(fmaf(dv, a6, b1.z), 0.f), fmaxf(fmaf(dv, a7, b1.w), 0.f));
    *reinterpret_cast<uint4*>(&g_zh[v * 32 + ql * 4]) = *reinterpret_cast<uint4*>(h);
}

// shared HMMA stage: out = Zs(fp16, 72-stride) @ Ws(fp16, 72-stride);
// messages dst[v] = half(dinv*out). 8 warps: 4 m-tiles x 2 n-tiles.
__device__ __forceinline__ void mma_stage(const __half* Zs, const __half* Ws,
                                          const float* dvs, int base, int n,
                                          int tid, __half2* __restrict__ dst) {
    int lane = tid & 31, wid = tid >> 5;
    int mt = wid & 3, nt = wid >> 2;
    float acc[4][4] = {};
    unsigned zbase = (unsigned)__cvta_generic_to_shared(Zs);
    unsigned wbase = (unsigned)__cvta_generic_to_shared(Ws);
    #pragma unroll
    for (int k = 0; k < 4; k++) {
        unsigned a0, a1, a2, a3;
        int arow = mt * 16 + (lane & 15);
        ldsm_x4(a0, a1, a2, a3, zbase + (arow * 72 + k * 16 + (lane >> 4) * 8) * 2);
        #pragma unroll
        for (int t = 0; t < 4; t++) {
            unsigned b0, b1;
            int brow = k * 16 + (lane & 15);
            ldsm_x2_t(b0, b1, wbase + (brow * 72 + nt * 32 + t * 8) * 2);
            mma_16816(acc[t], a0, a1, a2, a3, b0, b1);
        }
    }
    int r0 = mt * 16 + (lane >> 2), r1 = r0 + 8;
    int cp = lane & 3;
    float dv0 = dvs[r0], dv1 = dvs[r1];
    int v0 = base + r0, v1 = base + r1;
    #pragma unroll
    for (int t = 0; t < 4; t++) {
        int colpair = nt * 16 + t * 4 + cp;
        if (v0 < n)
            dst[v0 * 32 + colpair] = __floats2half2_rn(dv0 * acc[t][0], dv0 * acc[t][1]);
        if (v1 < n)
            dst[v1 * 32 + colpair] = __floats2half2_rn(dv1 * acc[t][2], dv1 * acc[t][3]);
    }
}

// layer 1: z1 = relu(dinv*(agg@W1)+b1) (fp32, 9-dim); msgs = half(dinv*(z1@W2)) via HMMA
__global__ __launch_bounds__(256) void k_l1_mma(const float* __restrict__ W1,
                                                const float* __restrict__ b1,
                                                const float* __restrict__ W2, int n) {
    __shared__ float W1s[9 * 64];
    __shared__ float A9s[64 * 16];
    __shared__ float dvs[64];
    __shared__ float b1s[64];
    __shared__ __half Zs[64 * 72];
    __shared__ __half Ws[64 * 72];
    int tid = threadIdx.x;
    int base = blockIdx.x * 64;
    for (int i = tid; i < 576; i += 256) W1s[i] = W1[i];
    if (tid < 64) {
        int v = base + tid;
        dvs[tid] = (v < n) ? g_dinv[v] : 0.f;
        b1s[tid] = b1[tid];
    }
    for (int i = tid; i < 4096; i += 256) {
        int k = i >> 6, f = i & 63;
        Ws[k * 72 + f] = __float2half(W2[i]);
    }
    for (int i = tid; i < 1024; i += 256) {
        int nl = i >> 4, k = i & 15;
        int v = base + nl;
        A9s[i] = (v < n) ? g_agg[v * 16 + k] : 0.f;
    }
    __syncthreads();
    for (int i = tid; i < 4096; i += 256) {
        int nl = i >> 6, f = i & 63;
        float s = 0.f;
        #pragma unroll
        for (int k = 0; k < 9; k++) s = fmaf(A9s[nl * 16 + k], W1s[k * 64 + f], s);
        Zs[nl * 72 + f] = __float2half(fmaxf(fmaf(dvs[nl], s, b1s[f]), 0.f));
    }
    __syncthreads();
    mma_stage(Zs, Ws, dvs, base, n, tid, g_bufh);
}

// middle layer: msgs = half(dinv*(z@W)) via HMMA, z read fp16 from g_zh
__global__ __launch_bounds__(256) void k_tf_mma(const float* __restrict__ W, int n) {
    __shared__ __half Zs[64 * 72];
    __shared__ __half Ws[64 * 72];
    __shared__ float dvs[64];
    int tid = threadIdx.x;
    int base = blockIdx.x * 64;
    if (tid < 64) {
        int v = base + tid;
        dvs[tid] = (v < n) ? g_dinv[v] : 0.f;
    }
    for (int i = tid; i < 4096; i += 256) {
        int k = i >> 6, f = i & 63;
        Ws[k * 72 + f] = __float2half(W[i]);
    }
    for (int i = tid; i < 512; i += 256) {
        int r = i >> 3, q = i & 7;
        int v = base + r;
        uint4 val = (v < n) ? *reinterpret_cast<const uint4*>(&g_zh[v * 32 + q * 4])
                            : make_uint4(0, 0, 0, 0);
        *reinterpret_cast<uint4*>(&Zs[r * 72 + q * 8]) = val;
    }
    __syncthreads();
    mma_stage(Zs, Ws, dvs, base, n, tid, g_bufh);
}

// pooling + head: h3 fp16 in g_zh; 32 partials x 32 feat-pairs
__global__ __launch_bounds__(1024) void k_pool(const float* __restrict__ Wl,
                                               const float* __restrict__ bl,
                                               float* __restrict__ outp) {
    __shared__ float ssum[32][64];
    __shared__ float smax[32][64];
    __shared__ float pooled[128];
    int g = blockIdx.x, tid = threadIdx.x;
    int fp = tid & 31, part = tid >> 5;
    int beg = g_goff[g], cnt = g_gcnt[g];
    float sx = 0.f, sy = 0.f, mx = 0.f, my = 0.f;
    for (int i = part; i < cnt; i += 32) {
        int v = beg + i;
        float2 h = __half22float2(__ldg(&g_zh[v * 32 + fp]));
        sx += h.x; sy += h.y;
        mx = fmaxf(mx, h.x); my = fmaxf(my, h.y);
    }
    ssum[part][fp * 2] = sx; ssum[part][fp * 2 + 1] = sy;
    smax[part][fp * 2] = mx; smax[part][fp * 2 + 1] = my;
    __syncthreads();
    if (tid < 64) {
        float s = 0.f, m = 0.f;
        #pragma unroll
        for (int w = 0; w < 32; w++) {
            s += ssum[w][tid];
            m = fmaxf(m, smax[w][tid]);
        }
        pooled[tid] = s / fmaxf((float)cnt, 1.f);
        pooled[64 + tid] = m;
    }
    __syncthreads();
    if (tid < 64) {
        float o = bl[tid];
        #pragma unroll 8
        for (int k = 0; k < 128; k++) o = fmaf(pooled[k], Wl[k * 64 + tid], o);
        outp[g * 64 + tid] = o;
    }
}

// -------------------- launcher --------------------

extern "C" void kernel_launch(void* const* d_in, const int* in_sizes, int n_in,
                              void* d_out, int out_size) {
    const float* x     = (const float*)d_in[0];
    const int*   ei    = (const int*)  d_in[1];
    const int*   batch = (const int*)  d_in[3];
    const float* W1    = (const float*)d_in[4];
    const float* b1    = (const float*)d_in[5];
    const float* W2    = (const float*)d_in[6];
    const float* b2    = (const float*)d_in[7];
    const float* W3    = (const float*)d_in[8];
    const float* b3    = (const float*)d_in[9];
    const float* Wl    = (const float*)d_in[10];
    const float* bl    = (const float*)d_in[11];
    float* out = (float*)d_out;

    int n = in_sizes[0] / 9;
    int e = in_sizes[1] / 2;
    const int* src = ei;
    const int* dst = ei + e;

    int gn  = (n + 255) / 256;
    int nb  = (n + 1023) / 1024;
    int ge4 = (e / 4 + 255) / 256 + 1;
    int gw4 = ((n + 3) / 4 * 32 + 255) / 256;

    // side stream + events, created once on the first (uncaptured) call
    static cudaStream_t s2 = nullptr;
    static cudaEvent_t ev_fork = nullptr, ev_join = nullptr;
    if (!s2) {
        cudaStreamCreateWithFlags(&s2, cudaStreamNonBlocking);
        cudaEventCreateWithFlags(&ev_fork, cudaEventDisableTiming);
        cudaEventCreateWithFlags(&ev_join, cudaEventDisableTiming);
    }

    // graph structure
    k_zero<<<gn, 256>>>(n);
    k_count<<<ge4, 256>>>(dst, batch, n, e);
    k_scanA<<<nb + 1, 1024>>>(n, nb);

    // fork: fill (needs only scanA) runs on s2, concurrent with scanC
    cudaEventRecord(ev_fork, 0);
    cudaStreamWaitEvent(s2, ev_fork, 0);
    k_fill<<<ge4, 256, 0, s2>>>(src, dst, e, nb);
    cudaEventRecord(ev_join, s2);

    k_scanC<<<gn, 256>>>(x, n, nb);

    // join before gathers (need both csr and rowptr2/xsh)
    cudaStreamWaitEvent(0, ev_join, 0);

    // layer 1: 9-dim gather + (W1, relu, W2) transform -> messages
    k_gather9h<<<gw4, 256>>>(n);
    k_l1_mma<<<(n + 63) / 64, 256>>>(W1, b1, W2, n);
    // layer 2: gather + epilogue(b2) -> z2; z2@W3 -> messages
    k_gather_z<<<gw4, 256>>>(b2, n);
    k_tf_mma<<<(n + 63) / 64, 256>>>(W3, n);
    // layer 3: gather + epilogue(b3) -> h3
    k_gather_z<<<gw4, 256>>>(b3, n);
    // pooling + head
    k_pool<<<GMAX, 1024>>>(Wl, bl, out);
}

// round 15
// speedup vs baseline: 1.0723x; 1.0517x over previous
#include <cuda_runtime.h>
#include <cuda_fp16.h>

#define NMAX 200000
#define EMAX 3200000
#define GMAX 1024
#define NBIN 512

// ---- scratch (static device globals; no runtime allocation) ----
__device__ int     g_cnt[NMAX];
__device__ int     g_rowptr[NMAX + 1];
__device__ int     g_rank[EMAX];
__device__ int     g_csr[EMAX];
__device__ int     g_bsums[1024];
__device__ int     g_gcnt[GMAX];
__device__ int     g_goff[GMAX];
__device__ int     g_dhist[NBIN];      // degree histogram
__device__ int     g_hoff[NBIN];       // descending-degree bin offsets
__device__ int     g_brnk[NMAX];       // node's rank within its degree bin
__device__ int     g_perm[NMAX];       // nodes in descending-degree order
__device__ float   g_dinv[NMAX];
__device__ __half2 g_xsh[NMAX * 8];    // layer-1 messages: 16 halves/row (9 real)
__device__ float   g_agg[NMAX * 16];   // layer-1 aggregated sums (fp32)
__device__ __half2 g_bufh[NMAX * 32];  // fp16 messages
__device__ __half2 g_zh[NMAX * 32];    // fp16 post-activation z (and final h3)

// -------------------- mma helpers --------------------

__device__ __forceinline__ void ldsm_x4(unsigned& a0, unsigned& a1, unsigned& a2,
                                        unsigned& a3, unsigned addr) {
    asm volatile("ldmatrix.sync.aligned.m8n8.x4.shared.b16 {%0,%1,%2,%3}, [%4];"
                 : "=r"(a0), "=r"(a1), "=r"(a2), "=r"(a3) : "r"(addr));
}
__device__ __forceinline__ void ldsm_x2_t(unsigned& b0, unsigned& b1, unsigned addr) {
    asm volatile("ldmatrix.sync.aligned.m8n8.x2.trans.shared.b16 {%0,%1}, [%2];"
                 : "=r"(b0), "=r"(b1) : "r"(addr));
}
__device__ __forceinline__ void mma_16816(float* c, unsigned a0, unsigned a1,
                                          unsigned a2, unsigned a3,
                                          unsigned b0, unsigned b1) {
    asm volatile("mma.sync.aligned.m16n8k16.row.col.f32.f16.f16.f32 "
                 "{%0,%1,%2,%3}, {%4,%5,%6,%7}, {%8,%9}, {%0,%1,%2,%3};"
                 : "+f"(c[0]), "+f"(c[1]), "+f"(c[2]), "+f"(c[3])
                 : "r"(a0), "r"(a1), "r"(a2), "r"(a3), "r"(b0), "r"(b1));
}

// -------------------- setup kernels --------------------

__global__ void k_zero(int n) {
    int i = blockIdx.x * blockDim.x + threadIdx.x;
    if (i < n) g_cnt[i] = 0;
    if (i < GMAX) g_gcnt[i] = 0;
    if (i < NBIN) g_dhist[i] = 0;
}

__global__ void k_count(const int* __restrict__ dst, const int* __restrict__ batch,
                        int n, int e) {
    int i = blockIdx.x * blockDim.x + threadIdx.x;
    int e4 = i * 4;
    if (e4 + 4 <= e) {
        int4 d = *reinterpret_cast<const int4*>(&dst[e4]);
        int4 r;
        r.x = atomicAdd(&g_cnt[d.x], 1);
        r.y = atomicAdd(&g_cnt[d.y], 1);
        r.z = atomicAdd(&g_cnt[d.z], 1);
        r.w = atomicAdd(&g_cnt[d.w], 1);
        *reinterpret_cast<int4*>(&g_rank[e4]) = r;
    } else {
        for (int q = e4; q < e; q++) g_rank[q] = atomicAdd(&g_cnt[dst[q]], 1);
    }
    int n4 = i * 4;
    if (n4 + 4 <= n) {
        int4 b = *reinterpret_cast<const int4*>(&batch[n4]);
        atomicAdd(&g_gcnt[b.x], 1);
        atomicAdd(&g_gcnt[b.y], 1);
        atomicAdd(&g_gcnt[b.z], 1);
        atomicAdd(&g_gcnt[b.w], 1);
    } else {
        for (int q = n4; q < n; q++) atomicAdd(&g_gcnt[batch[q]], 1);
    }
}

// per-1024-block scan of cnt (+ hierarchical degree histogram & within-bin ranks);
// extra last block performs the graph-offset scan
__global__ void k_scanA(int n, int nb) {
    __shared__ int s[1024];
    int t = threadIdx.x;
    if ((int)blockIdx.x == nb) {
        int v = g_gcnt[t];
        s[t] = v;
        __syncthreads();
        #pragma unroll
        for (int off = 1; off < 1024; off <<= 1) {
            int u = (t >= off) ? s[t - off] : 0;
            __syncthreads();
            s[t] += u;
            __syncthreads();
        }
        g_goff[t] = s[t] - v;
        return;
    }
    __shared__ int shist[NBIN];
    __shared__ int sbase[NBIN];
    if (t < NBIN) shist[t] = 0;
    __syncthreads();
    int i = blockIdx.x * 1024 + t;
    int v = (i < n) ? g_cnt[i] : 0;
    int lrank = 0, bin = 0;
    if (i < n) {
        bin = v < NBIN ? v : NBIN - 1;
        lrank = atomicAdd(&shist[bin], 1);
    }
    s[t] = v;
    __syncthreads();
    // publish block's per-bin counts to global hist; record block base per bin
    if (t < NBIN) {
        int c = shist[t];
        sbase[t] = c ? atomicAdd(&g_dhist[t], c) : 0;
    }
    #pragma unroll
    for (int off = 1; off < 1024; off <<= 1) {
        int u = (t >= off) ? s[t - off] : 0;
        __syncthreads();
        s[t] += u;
        __syncthreads();
    }
    if (i < n) {
        g_rowptr[i] = s[t] - v;
        g_brnk[i] = sbase[bin] + lrank;
    }
    if (t == 1023) g_bsums[blockIdx.x] = s[1023];
}

// descending-degree exclusive offsets of the 512 bins (1 block)
__global__ void k_hscan() {
    __shared__ int s[NBIN];
    int t = threadIdx.x;
    int idx = NBIN - 1 - t;             // t=0 <-> highest bin
    int v = g_dhist[idx];
    s[t] = v;
    __syncthreads();
    #pragma unroll
    for (int off = 1; off < NBIN; off <<= 1) {
        int u = (t >= off) ? s[t - off] : 0;
        __syncthreads();
        s[t] += u;
        __syncthreads();
    }
    g_hoff[idx] = s[t] - v;             // exclusive (descending order)
}

// fused: scan block sums in-block, finalize rowptr, dinv, fp16 xs messages, perm scatter
__global__ void k_scanC(const float* __restrict__ x, int n, int nb) {
    __shared__ int sb[256];
    __shared__ int sbx[256];
    int t = threadIdx.x;
    int bv = (t < nb) ? g_bsums[t] : 0;
    sb[t] = bv;
    __syncthreads();
    #pragma unroll
    for (int off = 1; off < 256; off <<= 1) {
        int u = (t >= off) ? sb[t - off] : 0;
        __syncthreads();
        sb[t] += u;
        __syncthreads();
    }
    sbx[t] = sb[t] - bv;
    __syncthreads();
    int i = blockIdx.x * 256 + t;
    if (i < n) {
        g_rowptr[i] += sbx[i >> 10];
        int c = g_cnt[i];
        int bin = c < NBIN ? c : NBIN - 1;
        g_perm[g_hoff[bin] + g_brnk[i]] = i;
        float dv = rsqrtf((float)(c + 1));
        g_dinv[i] = dv;
        __half2 h[8];
        #pragma unroll
        for (int k = 0; k < 8; k++) {
            float f0 = (2 * k     < 9) ? dv * x[i * 9 + 2 * k]     : 0.f;
            float f1 = (2 * k + 1 < 9) ? dv * x[i * 9 + 2 * k + 1] : 0.f;
            h[k] = __floats2half2_rn(f0, f1);
        }
        *reinterpret_cast<uint4*>(&g_xsh[i * 8])     = *reinterpret_cast<uint4*>(&h[0]);
        *reinterpret_cast<uint4*>(&g_xsh[i * 8 + 4]) = *reinterpret_cast<uint4*>(&h[4]);
    }
    if (blockIdx.x == 0 && t == 0) g_rowptr[n] = sb[255];
}

__global__ void k_fill(const int* __restrict__ src, const int* __restrict__ dst, int e) {
    int i = blockIdx.x * blockDim.x + threadIdx.x;
    int e4 = i * 4;
    if (e4 + 4 <= e) {
        int4 d = *reinterpret_cast<const int4*>(&dst[e4]);
        int4 s = *reinterpret_cast<const int4*>(&src[e4]);
        int4 r = *reinterpret_cast<const int4*>(&g_rank[e4]);
        g_csr[__ldg(&g_rowptr[d.x]) + r.x] = s.x;
        g_csr[__ldg(&g_rowptr[d.y]) + r.y] = s.y;
        g_csr[__ldg(&g_rowptr[d.z]) + r.z] = s.z;
        g_csr[__ldg(&g_rowptr[d.w]) + r.w] = s.w;
    } else {
        for (int q = e4; q < e; q++)
            g_csr[__ldg(&g_rowptr[dst[q]]) + g_rank[q]] = src[q];
    }
}

// -------------------- layer kernels --------------------

// layer-1 fp16 aggregation: 4 nodes per warp (degree-ordered); 8 lanes per node (half2)
__global__ __launch_bounds__(256) void k_gather9h(int n) {
    int gw = (blockIdx.x * blockDim.x + threadIdx.x) >> 5;
    int lane = threadIdx.x & 31;
    int grp = lane >> 3, gl = lane & 7;
    int idx = gw * 4 + grp;
    if (idx >= n) return;
    int v = __ldg(&g_perm[idx]);
    int beg = g_rowptr[v], end = g_rowptr[v + 1];
    float2 p = __half22float2(__ldg(&g_xsh[v * 8 + gl]));
    float ax = p.x, ay = p.y;
    int e = beg;
    for (; e + 8 <= end; e += 8) {
        int s[8];
        #pragma unroll
        for (int q = 0; q < 8; q++) s[q] = __ldg(&g_csr[e + q]);
        #pragma unroll
        for (int q = 0; q < 8; q++) {
            float2 w = __half22float2(__ldg(&g_xsh[s[q] * 8 + gl]));
            ax += w.x; ay += w.y;
        }
    }
    for (; e < end; e++) {
        int s = __ldg(&g_csr[e]);
        float2 w = __half22float2(__ldg(&g_xsh[s * 8 + gl]));
        ax += w.x; ay += w.y;
    }
    *reinterpret_cast<float2*>(&g_agg[v * 16 + gl * 2]) = make_float2(ax, ay);
}

// fp16 gather + fused epilogue: z[v] = relu(dinv*(self+neighbors) + bias), fp16 out
// 4 degree-ordered nodes per warp; 8 lanes per node, each lane covers 8 feats (uint4)
__global__ __launch_bounds__(256) void k_gather_z(const float* __restrict__ bias, int n) {
    int gw = (blockIdx.x * blockDim.x + threadIdx.x) >> 5;
    int lane = threadIdx.x & 31;
    int quad = lane >> 3, ql = lane & 7;
    int idx = gw * 4 + quad;
    if (idx >= n) return;
    int v = __ldg(&g_perm[idx]);
    int beg = g_rowptr[v], end = g_rowptr[v + 1];
    const uint4* buf = reinterpret_cast<const uint4*>(g_bufh);
    uint4 u = __ldg(&buf[v * 8 + ql]);   // self-loop
    float2 p0 = __half22float2(*reinterpret_cast<__half2*>(&u.x));
    float2 p1 = __half22float2(*reinterpret_cast<__half2*>(&u.y));
    float2 p2 = __half22float2(*reinterpret_cast<__half2*>(&u.z));
    float2 p3 = __half22float2(*reinterpret_cast<__half2*>(&u.w));
    float a0 = p0.x, a1 = p0.y, a2 = p1.x, a3 = p1.y;
    float a4 = p2.x, a5 = p2.y, a6 = p3.x, a7 = p3.y;
    int e = beg;
    for (; e + 8 <= end; e += 8) {
        int s[8];
        #pragma unroll
        for (int q = 0; q < 8; q++) s[q] = __ldg(&g_csr[e + q]);
        #pragma unroll
        for (int q = 0; q < 8; q++) {
            uint4 w = __ldg(&buf[s[q] * 8 + ql]);
            float2 q0 = __half22float2(*reinterpret_cast<__half2*>(&w.x));
            float2 q1 = __half22float2(*reinterpret_cast<__half2*>(&w.y));
            float2 q2 = __half22float2(*reinterpret_cast<__half2*>(&w.z));
            float2 q3 = __half22float2(*reinterpret_cast<__half2*>(&w.w));
            a0 += q0.x; a1 += q0.y; a2 += q1.x; a3 += q1.y;
            a4 += q2.x; a5 += q2.y; a6 += q3.x; a7 += q3.y;
        }
    }
    for (; e < end; e++) {
        int s = __ldg(&g_csr[e]);
        uint4 w = __ldg(&buf[s * 8 + ql]);
        float2 q0 = __half22float2(*reinterpret_cast<__half2*>(&w.x));
        float2 q1 = __half22float2(*reinterpret_cast<__half2*>(&w.y));
        float2 q2 = __half22float2(*reinterpret_cast<__half2*>(&w.z));
        float2 q3 = __half22float2(*reinterpret_cast<__half2*>(&w.w));
        a0 += q0.x; a1 += q0.y; a2 += q1.x; a3 += q1.y;
        a4 += q2.x; a5 += q2.y; a6 += q3.x; a7 += q3.y;
    }
    // fused epilogue: z = relu(dinv*a + b) in fp16
    float dv = g_dinv[v];
    float4 b0 = __ldg(&reinterpret_cast<const float4*>(bias)[ql * 2]);
    float4 b1 = __ldg(&reinterpret_cast<const float4*>(bias)[ql * 2 + 1]);
    __half2 h[4];
    h[0] = __floats2half2_rn(fmaxf(fmaf(dv, a0, b0.x), 0.f), fmaxf(fmaf(dv, a1, b0.y), 0.f));
    h[1] = __floats2half2_rn(fmaxf(fmaf(dv, a2, b0.z), 0.f), fmaxf(fmaf(dv, a3, b0.w), 0.f));
    h[2] = __floats2half2_rn(fmaxf(fmaf(dv, a4, b1.x), 0.f), fmaxf(fmaf(dv, a5, b1.y), 0.f));
    h[3] = __floats2half2_rn(fmaxf(fmaf(dv, a6, b1.z), 0.f), fmaxf(fmaf(dv, a7, b1.w), 0.f));
    *reinterpret_cast<uint4*>(&g_zh[v * 32 + ql * 4]) = *reinterpret_cast<uint4*>(h);
}

// shared HMMA stage: out = Zs(fp16, 72-stride) @ Ws(fp16, 72-stride);
// messages dst[v] = half(dinv*out). 8 warps: 4 m-tiles x 2 n-tiles.
__device__ __forceinline__ void mma_stage(const __half* Zs, const __half* Ws,
                                          const float* dvs, int base, int n,
                                          int tid, __half2* __restrict__ dst) {
    int lane = tid & 31, wid = tid >> 5;
    int mt = wid & 3, nt = wid >> 2;
    float acc[4][4] = {};
    unsigned zbase = (unsigned)__cvta_generic_to_shared(Zs);
    unsigned wbase = (unsigned)__cvta_generic_to_shared(Ws);
    #pragma unroll
    for (int k = 0; k < 4; k++) {
        unsigned a0, a1, a2, a3;
        int arow = mt * 16 + (lane & 15);
        ldsm_x4(a0, a1, a2, a3, zbase + (arow * 72 + k * 16 + (lane >> 4) * 8) * 2);
        #pragma unroll
        for (int t = 0; t < 4; t++) {
            unsigned b0, b1;
            int brow = k * 16 + (lane & 15);
            ldsm_x2_t(b0, b1, wbase + (brow * 72 + nt * 32 + t * 8) * 2);
            mma_16816(acc[t], a0, a1, a2, a3, b0, b1);
        }
    }
    int r0 = mt * 16 + (lane >> 2), r1 = r0 + 8;
    int cp = lane & 3;
    float dv0 = dvs[r0], dv1 = dvs[r1];
    int v0 = base + r0, v1 = base + r1;
    #pragma unroll
    for (int t = 0; t < 4; t++) {
        int colpair = nt * 16 + t * 4 + cp;
        if (v0 < n)
            dst[v0 * 32 + colpair] = __floats2half2_rn(dv0 * acc[t][0], dv0 * acc[t][1]);
        if (v1 < n)
            dst[v1 * 32 + colpair] = __floats2half2_rn(dv1 * acc[t][2], dv1 * acc[t][3]);
    }
}

// layer 1: z1 = relu(dinv*(agg@W1)+b1) (fp32, 9-dim); msgs = half(dinv*(z1@W2)) via HMMA
__global__ __launch_bounds__(256) void k_l1_mma(const float* __restrict__ W1,
                                                const float* __restrict__ b1,
                                                const float* __restrict__ W2, int n) {
    __shared__ float W1s[9 * 64];
    __shared__ float A9s[64 * 16];
    __shared__ float dvs[64];
    __shared__ float b1s[64];
    __shared__ __half Zs[64 * 72];
    __shared__ __half Ws[64 * 72];
    int tid = threadIdx.x;
    int base = blockIdx.x * 64;
    for (int i = tid; i < 576; i += 256) W1s[i] = W1[i];
    if (tid < 64) {
        int v = base + tid;
        dvs[tid] = (v < n) ? g_dinv[v] : 0.f;
        b1s[tid] = b1[tid];
    }
    for (int i = tid; i < 4096; i += 256) {
        int k = i >> 6, f = i & 63;
        Ws[k * 72 + f] = __float2half(W2[i]);
    }
    for (int i = tid; i < 1024; i += 256) {
        int nl = i >> 4, k = i & 15;
        int v = base + nl;
        A9s[i] = (v < n) ? g_agg[v * 16 + k] : 0.f;
    }
    __syncthreads();
    for (int i = tid; i < 4096; i += 256) {
        int nl = i >> 6, f = i & 63;
        float s = 0.f;
        #pragma unroll
        for (int k = 0; k < 9; k++) s = fmaf(A9s[nl * 16 + k], W1s[k * 64 + f], s);
        Zs[nl * 72 + f] = __float2half(fmaxf(fmaf(dvs[nl], s, b1s[f]), 0.f));
    }
    __syncthreads();
    mma_stage(Zs, Ws, dvs, base, n, tid, g_bufh);
}

// middle layer: msgs = half(dinv*(z@W)) via HMMA, z read fp16 from g_zh
__global__ __launch_bounds__(256) void k_tf_mma(const float* __restrict__ W, int n) {
    __shared__ __half Zs[64 * 72];
    __shared__ __half Ws[64 * 72];
    __shared__ float dvs[64];
    int tid = threadIdx.x;
    int base = blockIdx.x * 64;
    if (tid < 64) {
        int v = base + tid;
        dvs[tid] = (v < n) ? g_dinv[v] : 0.f;
    }
    for (int i = tid; i < 4096; i += 256) {
        int k = i >> 6, f = i & 63;
        Ws[k * 72 + f] = __float2half(W[i]);
    }
    for (int i = tid; i < 512; i += 256) {
        int r = i >> 3, q = i & 7;
        int v = base + r;
        uint4 val = (v < n) ? *reinterpret_cast<const uint4*>(&g_zh[v * 32 + q * 4])
                            : make_uint4(0, 0, 0, 0);
        *reinterpret_cast<uint4*>(&Zs[r * 72 + q * 8]) = val;
    }
    __syncthreads();
    mma_stage(Zs, Ws, dvs, base, n, tid, g_bufh);
}

// pooling + head: h3 fp16 in g_zh; 32 partials x 32 feat-pairs
__global__ __launch_bounds__(1024) void k_pool(const float* __restrict__ Wl,
                                               const float* __restrict__ bl,
                                               float* __restrict__ outp) {
    __shared__ float ssum[32][64];
    __shared__ float smax[32][64];
    __shared__ float pooled[128];
    int g = blockIdx.x, tid = threadIdx.x;
    int fp = tid & 31, part = tid >> 5;
    int beg = g_goff[g], cnt = g_gcnt[g];
    float sx = 0.f, sy = 0.f, mx = 0.f, my = 0.f;
    for (int i = part; i < cnt; i += 32) {
        int v = beg + i;
        float2 h = __half22float2(__ldg(&g_zh[v * 32 + fp]));
        sx += h.x; sy += h.y;
        mx = fmaxf(mx, h.x); my = fmaxf(my, h.y);
    }
    ssum[part][fp * 2] = sx; ssum[part][fp * 2 + 1] = sy;
    smax[part][fp * 2] = mx; smax[part][fp * 2 + 1] = my;
    __syncthreads();
    if (tid < 64) {
        float s = 0.f, m = 0.f;
        #pragma unroll
        for (int w = 0; w < 32; w++) {
            s += ssum[w][tid];
            m = fmaxf(m, smax[w][tid]);
        }
        pooled[tid] = s / fmaxf((float)cnt, 1.f);
        pooled[64 + tid] = m;
    }
    __syncthreads();
    if (tid < 64) {
        float o = bl[tid];
        #pragma unroll 8
        for (int k = 0; k < 128; k++) o = fmaf(pooled[k], Wl[k * 64 + tid], o);
        outp[g * 64 + tid] = o;
    }
}

// -------------------- launcher --------------------

extern "C" void kernel_launch(void* const* d_in, const int* in_sizes, int n_in,
                              void* d_out, int out_size) {
    const float* x     = (const float*)d_in[0];
    const int*   ei    = (const int*)  d_in[1];
    const int*   batch = (const int*)  d_in[3];
    const float* W1    = (const float*)d_in[4];
    const float* b1    = (const float*)d_in[5];
    const float* W2    = (const float*)d_in[6];
    const float* b2    = (const float*)d_in[7];
    const float* W3    = (const float*)d_in[8];
    const float* b3    = (const float*)d_in[9];
    const float* Wl    = (const float*)d_in[10];
    const float* bl    = (const float*)d_in[11];
    float* out = (float*)d_out;

    int n = in_sizes[0] / 9;
    int e = in_sizes[1] / 2;
    const int* src = ei;
    const int* dst = ei + e;

    int gn  = (n + 255) / 256;
    int nb  = (n + 1023) / 1024;
    int ge4 = (e / 4 + 255) / 256 + 1;
    int gw4 = ((n + 3) / 4 * 32 + 255) / 256;

    // graph structure
    k_zero<<<gn, 256>>>(n);
    k_count<<<ge4, 256>>>(dst, batch, n, e);
    k_scanA<<<nb + 1, 1024>>>(n, nb);
    k_hscan<<<1, NBIN>>>();
    k_scanC<<<gn, 256>>>(x, n, nb);
    k_fill<<<ge4, 256>>>(src, dst, e);

    // layer 1: 9-dim gather + (W1, relu, W2) transform -> messages
    k_gather9h<<<gw4, 256>>>(n);
    k_l1_mma<<<(n + 63) / 64, 256>>>(W1, b1, W2, n);
    // layer 2: gather + epilogue(b2) -> z2; z2@W3 -> messages
    k_gather_z<<<gw4, 256>>>(b2, n);
    k_tf_mma<<<(n + 63) / 64, 256>>>(W3, n);
    // layer 3: gather + epilogue(b3) -> h3
    k_gather_z<<<gw4, 256>>>(b3, n);
    // pooling + head
    k_pool<<<GMAX, 1024>>>(Wl, bl, out);
}

// round 16
// speedup vs baseline: 1.1235x; 1.0478x over previous
#include <cuda_runtime.h>
#include <cuda_fp16.h>

#define NMAX 200000
#define EMAX 3200000
#define GMAX 1024
#define NBIN 512

// ---- scratch (static device globals; no runtime allocation) ----
__device__ int     g_cnt[NMAX];
__device__ int     g_rowptr[NMAX + 1];
__device__ int     g_rank[EMAX];
__device__ int     g_csr[EMAX];
__device__ int     g_bsums[1024];
__device__ int     g_gcnt[GMAX];
__device__ int     g_goff[GMAX];
__device__ int     g_dhist[NBIN];      // degree histogram
__device__ int     g_brnk[NMAX];       // node's rank within its degree bin
__device__ int     g_perm[NMAX];       // nodes in descending-degree order
__device__ float   g_dinv[NMAX];
__device__ __half2 g_xsh[NMAX * 8];    // layer-1 messages: 16 halves/row (9 real)
__device__ float   g_agg[NMAX * 16];   // layer-1 aggregated sums (fp32)
__device__ __half2 g_bufh[NMAX * 32];  // fp16 messages
__device__ __half2 g_zh[NMAX * 32];    // fp16 post-activation z (and final h3)

// -------------------- mma helpers --------------------

__device__ __forceinline__ void ldsm_x4(unsigned& a0, unsigned& a1, unsigned& a2,
                                        unsigned& a3, unsigned addr) {
    asm volatile("ldmatrix.sync.aligned.m8n8.x4.shared.b16 {%0,%1,%2,%3}, [%4];"
                 : "=r"(a0), "=r"(a1), "=r"(a2), "=r"(a3) : "r"(addr));
}
__device__ __forceinline__ void ldsm_x2_t(unsigned& b0, unsigned& b1, unsigned addr) {
    asm volatile("ldmatrix.sync.aligned.m8n8.x2.trans.shared.b16 {%0,%1}, [%2];"
                 : "=r"(b0), "=r"(b1) : "r"(addr));
}
__device__ __forceinline__ void mma_16816(float* c, unsigned a0, unsigned a1,
                                          unsigned a2, unsigned a3,
                                          unsigned b0, unsigned b1) {
    asm volatile("mma.sync.aligned.m16n8k16.row.col.f32.f16.f16.f32 "
                 "{%0,%1,%2,%3}, {%4,%5,%6,%7}, {%8,%9}, {%0,%1,%2,%3};"
                 : "+f"(c[0]), "+f"(c[1]), "+f"(c[2]), "+f"(c[3])
                 : "r"(a0), "r"(a1), "r"(a2), "r"(a3), "r"(b0), "r"(b1));
}

// -------------------- setup kernels --------------------

__global__ void k_zero(int n) {
    int i = blockIdx.x * blockDim.x + threadIdx.x;
    if (i < n) g_cnt[i] = 0;
    if (i < NBIN) g_dhist[i] = 0;
}

// edge-side only: in-degree count + rank capture (batch handled by binary search)
__global__ void k_count(const int* __restrict__ dst, int e) {
    int i = blockIdx.x * blockDim.x + threadIdx.x;
    int e4 = i * 4;
    if (e4 + 4 <= e) {
        int4 d = *reinterpret_cast<const int4*>(&dst[e4]);
        int4 r;
        r.x = atomicAdd(&g_cnt[d.x], 1);
        r.y = atomicAdd(&g_cnt[d.y], 1);
        r.z = atomicAdd(&g_cnt[d.z], 1);
        r.w = atomicAdd(&g_cnt[d.w], 1);
        *reinterpret_cast<int4*>(&g_rank[e4]) = r;
    } else {
        for (int q = e4; q < e; q++) g_rank[q] = atomicAdd(&g_cnt[dst[q]], 1);
    }
}

// per-1024-block scan of cnt (+ degree histogram & within-bin ranks);
// extra last block computes graph offsets by binary search on sorted batch
__global__ void k_scanA(const int* __restrict__ batch, int n, int nb) {
    __shared__ int s[1024];
    int t = threadIdx.x;
    if ((int)blockIdx.x == nb) {
        // lower_bound(batch, n, t): first index with batch[idx] >= t
        int lo = 0, hi = n;
        while (lo < hi) {
            int mid = (lo + hi) >> 1;
            if (__ldg(&batch[mid]) < t) lo = mid + 1; else hi = mid;
        }
        s[t] = lo;
        __syncthreads();
        g_goff[t] = lo;
        g_gcnt[t] = ((t == GMAX - 1) ? n : s[t + 1]) - lo;
        return;
    }
    __shared__ int shist[NBIN];
    __shared__ int sbase[NBIN];
    if (t < NBIN) shist[t] = 0;
    __syncthreads();
    int i = blockIdx.x * 1024 + t;
    int v = (i < n) ? g_cnt[i] : 0;
    int lrank = 0, bin = 0;
    if (i < n) {
        bin = v < NBIN ? v : NBIN - 1;
        lrank = atomicAdd(&shist[bin], 1);
    }
    s[t] = v;
    __syncthreads();
    if (t < NBIN) {
        int c = shist[t];
        sbase[t] = c ? atomicAdd(&g_dhist[t], c) : 0;
    }
    #pragma unroll
    for (int off = 1; off < 1024; off <<= 1) {
        int u = (t >= off) ? s[t - off] : 0;
        __syncthreads();
        s[t] += u;
        __syncthreads();
    }
    if (i < n) {
        g_rowptr[i] = s[t] - v;
        g_brnk[i] = sbase[bin] + lrank;
    }
    if (t == 1023) g_bsums[blockIdx.x] = s[1023];
}

// fused: scan block sums + descending-degree bin offsets (both in-block),
// finalize rowptr, dinv, fp16 xs messages, perm scatter
__global__ void k_scanC(const float* __restrict__ x, int n, int nb) {
    __shared__ int sb[256];
    __shared__ int sbx[256];
    __shared__ int sps[256];       // pair-sum scan workspace for hoff
    __shared__ int shoff[NBIN];    // descending-degree exclusive bin offsets
    int t = threadIdx.x;
    // --- block-sum scan (nb <= 256) ---
    int bv = (t < nb) ? g_bsums[t] : 0;
    sb[t] = bv;
    // --- load descending bin pairs: position 2t <-> bin 511-2t, 2t+1 <-> 510-2t ---
    int hiBin = NBIN - 1 - 2 * t;
    int h0 = g_dhist[hiBin];
    int h1 = g_dhist[hiBin - 1];
    sps[t] = h0 + h1;
    __syncthreads();
    #pragma unroll
    for (int off = 1; off < 256; off <<= 1) {
        int u0 = (t >= off) ? sb[t - off] : 0;
        int u1 = (t >= off) ? sps[t - off] : 0;
        __syncthreads();
        sb[t] += u0;
        sps[t] += u1;
        __syncthreads();
    }
    sbx[t] = sb[t] - bv;
    int exc = sps[t] - (h0 + h1);    // exclusive prefix at descending position 2t
    shoff[hiBin]     = exc;
    shoff[hiBin - 1] = exc + h0;
    __syncthreads();
    int i = blockIdx.x * 256 + t;
    if (i < n) {
        g_rowptr[i] += sbx[i >> 10];
        int c = g_cnt[i];
        int bin = c < NBIN ? c : NBIN - 1;
        g_perm[shoff[bin] + g_brnk[i]] = i;
        float dv = rsqrtf((float)(c + 1));
        g_dinv[i] = dv;
        __half2 h[8];
        #pragma unroll
        for (int k = 0; k < 8; k++) {
            float f0 = (2 * k     < 9) ? dv * x[i * 9 + 2 * k]     : 0.f;
            float f1 = (2 * k + 1 < 9) ? dv * x[i * 9 + 2 * k + 1] : 0.f;
            h[k] = __floats2half2_rn(f0, f1);
        }
        *reinterpret_cast<uint4*>(&g_xsh[i * 8])     = *reinterpret_cast<uint4*>(&h[0]);
        *reinterpret_cast<uint4*>(&g_xsh[i * 8 + 4]) = *reinterpret_cast<uint4*>(&h[4]);
    }
    if (blockIdx.x == 0 && t == 0) g_rowptr[n] = sb[255];
}

__global__ void k_fill(const int* __restrict__ src, const int* __restrict__ dst, int e) {
    int i = blockIdx.x * blockDim.x + threadIdx.x;
    int e4 = i * 4;
    if (e4 + 4 <= e) {
        int4 d = *reinterpret_cast<const int4*>(&dst[e4]);
        int4 s = *reinterpret_cast<const int4*>(&src[e4]);
        int4 r = *reinterpret_cast<const int4*>(&g_rank[e4]);
        g_csr[__ldg(&g_rowptr[d.x]) + r.x] = s.x;
        g_csr[__ldg(&g_rowptr[d.y]) + r.y] = s.y;
        g_csr[__ldg(&g_rowptr[d.z]) + r.z] = s.z;
        g_csr[__ldg(&g_rowptr[d.w]) + r.w] = s.w;
    } else {
        for (int q = e4; q < e; q++)
            g_csr[__ldg(&g_rowptr[dst[q]]) + g_rank[q]] = src[q];
    }
}

// -------------------- layer kernels --------------------

// layer-1 fp16 aggregation: 4 degree-ordered nodes per warp; 8 lanes per node (half2)
__global__ __launch_bounds__(256) void k_gather9h(int n) {
    int gw = (blockIdx.x * blockDim.x + threadIdx.x) >> 5;
    int lane = threadIdx.x & 31;
    int grp = lane >> 3, gl = lane & 7;
    int idx = gw * 4 + grp;
    if (idx >= n) return;
    int v = __ldg(&g_perm[idx]);
    int beg = g_rowptr[v], end = g_rowptr[v + 1];
    float2 p = __half22float2(__ldg(&g_xsh[v * 8 + gl]));
    float ax = p.x, ay = p.y;
    int e = beg;
    for (; e + 8 <= end; e += 8) {
        int s[8];
        #pragma unroll
        for (int q = 0; q < 8; q++) s[q] = __ldg(&g_csr[e + q]);
        #pragma unroll
        for (int q = 0; q < 8; q++) {
            float2 w = __half22float2(__ldg(&g_xsh[s[q] * 8 + gl]));
            ax += w.x; ay += w.y;
        }
    }
    for (; e < end; e++) {
        int s = __ldg(&g_csr[e]);
        float2 w = __half22float2(__ldg(&g_xsh[s * 8 + gl]));
        ax += w.x; ay += w.y;
    }
    *reinterpret_cast<float2*>(&g_agg[v * 16 + gl * 2]) = make_float2(ax, ay);
}

// fp16 gather + fused epilogue: z[v] = relu(dinv*(self+neighbors) + bias), fp16 out
// 4 degree-ordered nodes per warp; 8 lanes per node, each lane covers 8 feats (uint4)
__global__ __launch_bounds__(256) void k_gather_z(const float* __restrict__ bias, int n) {
    int gw = (blockIdx.x * blockDim.x + threadIdx.x) >> 5;
    int lane = threadIdx.x & 31;
    int quad = lane >> 3, ql = lane & 7;
    int idx = gw * 4 + quad;
    if (idx >= n) return;
    int v = __ldg(&g_perm[idx]);
    int beg = g_rowptr[v], end = g_rowptr[v + 1];
    const uint4* buf = reinterpret_cast<const uint4*>(g_bufh);
    uint4 u = __ldg(&buf[v * 8 + ql]);   // self-loop
    float2 p0 = __half22float2(*reinterpret_cast<__half2*>(&u.x));
    float2 p1 = __half22float2(*reinterpret_cast<__half2*>(&u.y));
    float2 p2 = __half22float2(*reinterpret_cast<__half2*>(&u.z));
    float2 p3 = __half22float2(*reinterpret_cast<__half2*>(&u.w));
    float a0 = p0.x, a1 = p0.y, a2 = p1.x, a3 = p1.y;
    float a4 = p2.x, a5 = p2.y, a6 = p3.x, a7 = p3.y;
    int e = beg;
    for (; e + 8 <= end; e += 8) {
        int s[8];
        #pragma unroll
        for (int q = 0; q < 8; q++) s[q] = __ldg(&g_csr[e + q]);
        #pragma unroll
        for (int q = 0; q < 8; q++) {
            uint4 w = __ldg(&buf[s[q] * 8 + ql]);
            float2 q0 = __half22float2(*reinterpret_cast<__half2*>(&w.x));
            float2 q1 = __half22float2(*reinterpret_cast<__half2*>(&w.y));
            float2 q2 = __half22float2(*reinterpret_cast<__half2*>(&w.z));
            float2 q3 = __half22float2(*reinterpret_cast<__half2*>(&w.w));
            a0 += q0.x; a1 += q0.y; a2 += q1.x; a3 += q1.y;
            a4 += q2.x; a5 += q2.y; a6 += q3.x; a7 += q3.y;
        }
    }
    for (; e < end; e++) {
        int s = __ldg(&g_csr[e]);
        uint4 w = __ldg(&buf[s * 8 + ql]);
        float2 q0 = __half22float2(*reinterpret_cast<__half2*>(&w.x));
        float2 q1 = __half22float2(*reinterpret_cast<__half2*>(&w.y));
        float2 q2 = __half22float2(*reinterpret_cast<__half2*>(&w.z));
        float2 q3 = __half22float2(*reinterpret_cast<__half2*>(&w.w));
        a0 += q0.x; a1 += q0.y; a2 += q1.x; a3 += q1.y;
        a4 += q2.x; a5 += q2.y; a6 += q3.x; a7 += q3.y;
    }
    // fused epilogue: z = relu(dinv*a + b) in fp16
    float dv = g_dinv[v];
    float4 b0 = __ldg(&reinterpret_cast<const float4*>(bias)[ql * 2]);
    float4 b1 = __ldg(&reinterpret_cast<const float4*>(bias)[ql * 2 + 1]);
    __half2 h[4];
    h[0] = __floats2half2_rn(fmaxf(fmaf(dv, a0, b0.x), 0.f), fmaxf(fmaf(dv, a1, b0.y), 0.f));
    h[1] = __floats2half2_rn(fmaxf(fmaf(dv, a2, b0.z), 0.f), fmaxf(fmaf(dv, a3, b0.w), 0.f));
    h[2] = __floats2half2_rn(fmaxf(fmaf(dv, a4, b1.x), 0.f), fmaxf(fmaf(dv, a5, b1.y), 0.f));
    h[3] = __floats2half2_rn(fmaxf(fmaf(dv, a6, b1.z), 0.f), fmaxf(fmaf(dv, a7, b1.w), 0.f));
    *reinterpret_cast<uint4*>(&g_zh[v * 32 + ql * 4]) = *reinterpret_cast<uint4*>(h);
}

// shared HMMA stage: out = Zs(fp16, 72-stride) @ Ws(fp16, 72-stride);
// messages dst[v] = half(dinv*out). 8 warps: 4 m-tiles x 2 n-tiles.
__device__ __forceinline__ void mma_stage(const __half* Zs, const __half* Ws,
                                          const float* dvs, int base, int n,
                                          int tid, __half2* __restrict__ dst) {
    int lane = tid & 31, wid = tid >> 5;
    int mt = wid & 3, nt = wid >> 2;
    float acc[4][4] = {};
    unsigned zbase = (unsigned)__cvta_generic_to_shared(Zs);
    unsigned wbase = (unsigned)__cvta_generic_to_shared(Ws);
    #pragma unroll
    for (int k = 0; k < 4; k++) {
        unsigned a0, a1, a2, a3;
        int arow = mt * 16 + (lane & 15);
        ldsm_x4(a0, a1, a2, a3, zbase + (arow * 72 + k * 16 + (lane >> 4) * 8) * 2);
        #pragma unroll
        for (int t = 0; t < 4; t++) {
            unsigned b0, b1;
            int brow = k * 16 + (lane & 15);
            ldsm_x2_t(b0, b1, wbase + (brow * 72 + nt * 32 + t * 8) * 2);
            mma_16816(acc[t], a0, a1, a2, a3, b0, b1);
        }
    }
    int r0 = mt * 16 + (lane >> 2), r1 = r0 + 8;
    int cp = lane & 3;
    float dv0 = dvs[r0], dv1 = dvs[r1];
    int v0 = base + r0, v1 = base + r1;
    #pragma unroll
    for (int t = 0; t < 4; t++) {
        int colpair = nt * 16 + t * 4 + cp;
        if (v0 < n)
            dst[v0 * 32 + colpair] = __floats2half2_rn(dv0 * acc[t][0], dv0 * acc[t][1]);
        if (v1 < n)
            dst[v1 * 32 + colpair] = __floats2half2_rn(dv1 * acc[t][2], dv1 * acc[t][3]);
    }
}

// layer 1: z1 = relu(dinv*(agg@W1)+b1) (fp32, 9-dim); msgs = half(dinv*(z1@W2)) via HMMA
__global__ __launch_bounds__(256) void k_l1_mma(const float* __restrict__ W1,
                                                const float* __restrict__ b1,
                                                const float* __restrict__ W2, int n) {
    __shared__ float W1s[9 * 64];
    __shared__ float A9s[64 * 16];
    __shared__ float dvs[64];
    __shared__ float b1s[64];
    __shared__ __half Zs[64 * 72];
    __shared__ __half Ws[64 * 72];
    int tid = threadIdx.x;
    int base = blockIdx.x * 64;
    for (int i = tid; i < 576; i += 256) W1s[i] = W1[i];
    if (tid < 64) {
        int v = base + tid;
        dvs[tid] = (v < n) ? g_dinv[v] : 0.f;
        b1s[tid] = b1[tid];
    }
    for (int i = tid; i < 4096; i += 256) {
        int k = i >> 6, f = i & 63;
        Ws[k * 72 + f] = __float2half(W2[i]);
    }
    for (int i = tid; i < 1024; i += 256) {
        int nl = i >> 4, k = i & 15;
        int v = base + nl;
        A9s[i] = (v < n) ? g_agg[v * 16 + k] : 0.f;
    }
    __syncthreads();
    for (int i = tid; i < 4096; i += 256) {
        int nl = i >> 6, f = i & 63;
        float s = 0.f;
        #pragma unroll
        for (int k = 0; k < 9; k++) s = fmaf(A9s[nl * 16 + k], W1s[k * 64 + f], s);
        Zs[nl * 72 + f] = __float2half(fmaxf(fmaf(dvs[nl], s, b1s[f]), 0.f));
    }
    __syncthreads();
    mma_stage(Zs, Ws, dvs, base, n, tid, g_bufh);
}

// middle layer: msgs = half(dinv*(z@W)) via HMMA, z read fp16 from g_zh
__global__ __launch_bounds__(256) void k_tf_mma(const float* __restrict__ W, int n) {
    __shared__ __half Zs[64 * 72];
    __shared__ __half Ws[64 * 72];
    __shared__ float dvs[64];
    int tid = threadIdx.x;
    int base = blockIdx.x * 64;
    if (tid < 64) {
        int v = base + tid;
        dvs[tid] = (v < n) ? g_dinv[v] : 0.f;
    }
    for (int i = tid; i < 4096; i += 256) {
        int k = i >> 6, f = i & 63;
        Ws[k * 72 + f] = __float2half(W[i]);
    }
    for (int i = tid; i < 512; i += 256) {
        int r = i >> 3, q = i & 7;
        int v = base + r;
        uint4 val = (v < n) ? *reinterpret_cast<const uint4*>(&g_zh[v * 32 + q * 4])
                            : make_uint4(0, 0, 0, 0);
        *reinterpret_cast<uint4*>(&Zs[r * 72 + q * 8]) = val;
    }
    __syncthreads();
    mma_stage(Zs, Ws, dvs, base, n, tid, g_bufh);
}

// pooling + head: h3 fp16 in g_zh; 32 partials x 32 feat-pairs
__global__ __launch_bounds__(1024) void k_pool(const float* __restrict__ Wl,
                                               const float* __restrict__ bl,
                                               float* __restrict__ outp) {
    __shared__ float ssum[32][64];
    __shared__ float smax[32][64];
    __shared__ float pooled[128];
    int g = blockIdx.x, tid = threadIdx.x;
    int fp = tid & 31, part = tid >> 5;
    int beg = g_goff[g], cnt = g_gcnt[g];
    float sx = 0.f, sy = 0.f, mx = 0.f, my = 0.f;
    for (int i = part; i < cnt; i += 32) {
        int v = beg + i;
        float2 h = __half22float2(__ldg(&g_zh[v * 32 + fp]));
        sx += h.x; sy += h.y;
        mx = fmaxf(mx, h.x); my = fmaxf(my, h.y);
    }
    ssum[part][fp * 2] = sx; ssum[part][fp * 2 + 1] = sy;
    smax[part][fp * 2] = mx; smax[part][fp * 2 + 1] = my;
    __syncthreads();
    if (tid < 64) {
        float s = 0.f, m = 0.f;
        #pragma unroll
        for (int w = 0; w < 32; w++) {
            s += ssum[w][tid];
            m = fmaxf(m, smax[w][tid]);
        }
        pooled[tid] = s / fmaxf((float)cnt, 1.f);
        pooled[64 + tid] = m;
    }
    __syncthreads();
    if (tid < 64) {
        float o = bl[tid];
        #pragma unroll 8
        for (int k = 0; k < 128; k++) o = fmaf(pooled[k], Wl[k * 64 + tid], o);
        outp[g * 64 + tid] = o;
    }
}

// -------------------- launcher --------------------

extern "C" void kernel_launch(void* const* d_in, const int* in_sizes, int n_in,
                              void* d_out, int out_size) {
    const float* x     = (const float*)d_in[0];
    const int*   ei    = (const int*)  d_in[1];
    const int*   batch = (const int*)  d_in[3];
    const float* W1    = (const float*)d_in[4];
    const float* b1    = (const float*)d_in[5];
    const float* W2    = (const float*)d_in[6];
    const float* b2    = (const float*)d_in[7];
    const float* W3    = (const float*)d_in[8];
    const float* b3    = (const float*)d_in[9];
    const float* Wl    = (const float*)d_in[10];
    const float* bl    = (const float*)d_in[11];
    float* out = (float*)d_out;

    int n = in_sizes[0] / 9;
    int e = in_sizes[1] / 2;
    const int* src = ei;
    const int* dst = ei + e;

    int gn  = (n + 255) / 256;
    int nb  = (n + 1023) / 1024;
    int ge4 = (e / 4 + 255) / 256 + 1;
    int gw4 = ((n + 3) / 4 * 32 + 255) / 256;

    // graph structure
    k_zero<<<gn, 256>>>(n);
    k_count<<<ge4, 256>>>(dst, e);
    k_scanA<<<nb + 1, 1024>>>(batch, n, nb);   // extra block: goff/gcnt by binary search
    k_scanC<<<gn, 256>>>(x, n, nb);            // + in-block descending bin offsets
    k_fill<<<ge4, 256>>>(src, dst, e);

    // layer 1: 9-dim gather + (W1, relu, W2) transform -> messages
    k_gather9h<<<gw4, 256>>>(n);
    k_l1_mma<<<(n + 63) / 64, 256>>>(W1, b1, W2, n);
    // layer 2: gather + epilogue(b2) -> z2; z2@W3 -> messages
    k_gather_z<<<gw4, 256>>>(b2, n);
    k_tf_mma<<<(n + 63) / 64, 256>>>(W3, n);
    // layer 3: gather + epilogue(b3) -> h3
    k_gather_z<<<gw4, 256>>>(b3, n);
    // pooling + head
    k_pool<<<GMAX, 1024>>>(Wl, bl, out);
}